// round 1
// baseline (speedup 1.0000x reference)
#include <cuda_runtime.h>
#include <math.h>

#define S_   1024
#define B_   2
#define D_   1024
#define NH   16
#define DH   64
#define DI_  4096
#define R_   2048
#define SB   (S_*B_)          // 2048
#define RB   (R_*B_)          // 4096
#define ND   (NH*DH)          // 1024
#define NHEADS (B_*NH)        // 32

// ---------------- scratch (device globals; no allocation allowed) ----------------
__device__ float g_q   [SB*ND];
__device__ float g_k   [SB*ND];
__device__ float g_v   [SB*ND];
__device__ float g_kr  [RB*ND];
__device__ float g_ef  [SB*NH*2];
__device__ float g_score[(size_t)NHEADS*S_*S_];   // 128 MiB
__device__ float g_vec [SB*ND];
__device__ float g_attn[SB*ND];
__device__ float g_x   [SB*ND];
__device__ float g_f   [SB*DI_];
__device__ float g_f2  [SB*ND];
__device__ float g_buf [SB*ND];

enum { EPI_NONE = 0, EPI_BIAS = 1, EPI_BIAS_GELU = 2, EPI_RES = 3 };

__device__ __forceinline__ float gelu_f(float x) {
    return 0.5f * x * (1.0f + erff(x * 0.7071067811865476f));
}

// ---------------- generic 128x128 SGEMM, NN / NT, fused epilogues ----------------
template<int EPI, bool TB>
__global__ void __launch_bounds__(256) gemm128(
    const float* __restrict__ A, const float* __restrict__ Bm, float* __restrict__ C,
    int M, int Nn, int K, const float* __restrict__ bias, const float* __restrict__ res)
{
    __shared__ float As[8][132];
    __shared__ float Bs[8][132];
    const int tid = threadIdx.x;
    const int m0 = blockIdx.y * 128, n0 = blockIdx.x * 128;
    const int tx = tid & 15, ty = tid >> 4;
    const int lm  = tid >> 1;         // 0..127
    const int lkq = (tid & 1) * 4;    // 0 or 4
    const int bk  = tid >> 5;         // 0..7
    const int bn  = (tid & 31) * 4;   // 0..124

    float acc[8][8];
    #pragma unroll
    for (int i = 0; i < 8; i++)
        #pragma unroll
        for (int j = 0; j < 8; j++) acc[i][j] = 0.f;

    for (int k0 = 0; k0 < K; k0 += 8) {
        float4 av = *(const float4*)(A + (size_t)(m0 + lm) * K + k0 + lkq);
        As[lkq + 0][lm] = av.x; As[lkq + 1][lm] = av.y;
        As[lkq + 2][lm] = av.z; As[lkq + 3][lm] = av.w;
        if (TB) {
            float4 bv = *(const float4*)(Bm + (size_t)(n0 + lm) * K + k0 + lkq);
            Bs[lkq + 0][lm] = bv.x; Bs[lkq + 1][lm] = bv.y;
            Bs[lkq + 2][lm] = bv.z; Bs[lkq + 3][lm] = bv.w;
        } else {
            float4 bv = *(const float4*)(Bm + (size_t)(k0 + bk) * Nn + n0 + bn);
            *(float4*)&Bs[bk][bn] = bv;
        }
        __syncthreads();
        #pragma unroll
        for (int kk = 0; kk < 8; kk++) {
            float a[8], b8[8];
            *(float4*)(a)     = *(const float4*)&As[kk][ty * 8];
            *(float4*)(a + 4) = *(const float4*)&As[kk][ty * 8 + 4];
            *(float4*)(b8)     = *(const float4*)&Bs[kk][tx * 8];
            *(float4*)(b8 + 4) = *(const float4*)&Bs[kk][tx * 8 + 4];
            #pragma unroll
            for (int i = 0; i < 8; i++)
                #pragma unroll
                for (int j = 0; j < 8; j++)
                    acc[i][j] += a[i] * b8[j];
        }
        __syncthreads();
    }

    #pragma unroll
    for (int i = 0; i < 8; i++) {
        int m = m0 + ty * 8 + i;
        #pragma unroll
        for (int j = 0; j < 8; j++) {
            int n = n0 + tx * 8 + j;
            float v = acc[i][j];
            if (EPI == EPI_BIAS || EPI == EPI_BIAS_GELU) v += bias[n];
            if (EPI == EPI_BIAS_GELU) v = gelu_f(v);
            if (EPI == EPI_RES) v += res[(size_t)m * Nn + n];
            C[(size_t)m * Nn + n] = v;
        }
    }
}

// ---------------- ef[i,b,n,s] = (q + r_s_bias) . seg_embed[s] ----------------
__global__ void ef_kernel(const float* __restrict__ q, const float* __restrict__ rs,
                          const float* __restrict__ se, float* __restrict__ ef)
{
    int w = blockIdx.x * 4 + (threadIdx.x >> 5);   // over SB*NH
    int lane = threadIdx.x & 31;
    int row = w / NH, n = w % NH;
    int d0 = lane * 2;
    const float* qp = q + (size_t)row * ND + n * DH;
    float q0 = qp[d0]     + rs[n * DH + d0];
    float q1 = qp[d0 + 1] + rs[n * DH + d0 + 1];
    float s0 = q0 * se[(0 * NH + n) * DH + d0] + q1 * se[(0 * NH + n) * DH + d0 + 1];
    float s1 = q0 * se[(1 * NH + n) * DH + d0] + q1 * se[(1 * NH + n) * DH + d0 + 1];
    #pragma unroll
    for (int off = 16; off; off >>= 1) {
        s0 += __shfl_xor_sync(0xffffffffu, s0, off);
        s1 += __shfl_xor_sync(0xffffffffu, s1, off);
    }
    if (lane == 0) { ef[w * 2] = s0; ef[w * 2 + 1] = s1; }
}

// ---------------- fused relative-attention score ----------------
// score[i,j] = ((q+rw).k[j] + (q+rr).kr[S+j-i] + seg_mat.ef) * scale - 1e30*mask
__global__ void __launch_bounds__(256) score_kernel(
    const float* __restrict__ q, const float* __restrict__ k, const float* __restrict__ kr,
    const float* __restrict__ rw, const float* __restrict__ rr,
    const float* __restrict__ ef, const float* __restrict__ seg_mat,
    const float* __restrict__ attn_mask, float* __restrict__ score)
{
    const int head = blockIdx.z;
    const int b = head / NH, n = head % NH;
    const int i0 = blockIdx.y * 64, j0 = blockIdx.x * 64;
    float* sc = score + (size_t)head * S_ * S_;
    const int tid = threadIdx.x;

    if (j0 > i0) {  // fully masked tile
        for (int e = tid; e < 64 * 64; e += 256)
            sc[(size_t)(i0 + (e >> 6)) * S_ + j0 + (e & 63)] = -1e30f;
        return;
    }

    __shared__ float Qw[16][65], Qr[16][65], Kh[16][65], Krs[16][129];
    const int dl = tid & 15;
    const int lr = tid >> 4;
    const int r_base = S_ + j0 - i0 - 63;   // in [1, 961]
    const int tx = tid & 15, ty = tid >> 4;
    const int li0 = ty * 4, lj0 = tx * 4;

    float acc_ac[4][4], acc_bd[4][4];
    #pragma unroll
    for (int i = 0; i < 4; i++)
        #pragma unroll
        for (int j = 0; j < 4; j++) { acc_ac[i][j] = 0.f; acc_bd[i][j] = 0.f; }

    for (int kc = 0; kc < 4; kc++) {
        const int d0 = kc * 16;
        const float bw = rw[n * DH + d0 + dl];
        const float br = rr[n * DH + d0 + dl];
        #pragma unroll
        for (int s = 0; s < 4; s++) {
            int li = lr + s * 16;
            float qv = q[((size_t)((i0 + li) * B_ + b)) * ND + n * DH + d0 + dl];
            Qw[dl][li] = qv + bw;
            Qr[dl][li] = qv + br;
            Kh[dl][li] = k[((size_t)((j0 + li) * B_ + b)) * ND + n * DH + d0 + dl];
        }
        #pragma unroll
        for (int s = 0; s < 8; s++) {
            int lrr = lr + s * 16;
            Krs[dl][lrr] = kr[((size_t)((r_base + lrr) * B_ + b)) * ND + n * DH + d0 + dl];
        }
        __syncthreads();
        #pragma unroll
        for (int kk = 0; kk < 16; kk++) {
            float a[4], ar[4], bb[4];
            #pragma unroll
            for (int t = 0; t < 4; t++) {
                a[t]  = Qw[kk][li0 + t];
                ar[t] = Qr[kk][li0 + t];
                bb[t] = Kh[kk][lj0 + t];
            }
            #pragma unroll
            for (int i = 0; i < 4; i++)
                #pragma unroll
                for (int j = 0; j < 4; j++) {
                    acc_ac[i][j] += a[i] * bb[j];
                    acc_bd[i][j] += ar[i] * Krs[kk][lj0 + j - li0 - i + 63];
                }
        }
        __syncthreads();
    }

    const float scale = 0.125f;  // 1/sqrt(64)
    #pragma unroll
    for (int i = 0; i < 4; i++) {
        int gi = i0 + li0 + i;
        float ef0 = ef[((size_t)(gi * B_ + b) * NH + n) * 2 + 0];
        float ef1 = ef[((size_t)(gi * B_ + b) * NH + n) * 2 + 1];
        #pragma unroll
        for (int j = 0; j < 4; j++) {
            int gj = j0 + lj0 + j;
            const float* sm = seg_mat + (((size_t)gi * S_ + gj) * B_ + b) * 2;
            float msk = attn_mask[(size_t)gi * S_ + gj];
            float v = (acc_ac[i][j] + acc_bd[i][j] + sm[0] * ef0 + sm[1] * ef1) * scale
                      - 1e30f * msk;
            sc[(size_t)gi * S_ + gj] = v;
        }
    }
}

// ---------------- row softmax over j (length S) ----------------
__global__ void softmax_kernel(float* __restrict__ score)
{
    const int head = blockIdx.y, i = blockIdx.x;
    float* row = score + (size_t)head * S_ * S_ + (size_t)i * S_;
    __shared__ float red[256];
    const int tid = threadIdx.x;
    float v[4];
    float mx = -3.0e38f;
    #pragma unroll
    for (int t = 0; t < 4; t++) { v[t] = row[tid + t * 256]; mx = fmaxf(mx, v[t]); }
    red[tid] = mx; __syncthreads();
    for (int o = 128; o > 0; o >>= 1) { if (tid < o) red[tid] = fmaxf(red[tid], red[tid + o]); __syncthreads(); }
    mx = red[0]; __syncthreads();
    float s = 0.f;
    #pragma unroll
    for (int t = 0; t < 4; t++) { v[t] = expf(v[t] - mx); s += v[t]; }
    red[tid] = s; __syncthreads();
    for (int o = 128; o > 0; o >>= 1) { if (tid < o) red[tid] += red[tid + o]; __syncthreads(); }
    float inv = 1.0f / red[0];
    #pragma unroll
    for (int t = 0; t < 4; t++) row[tid + t * 256] = v[t] * inv;
}

// ---------------- vec = prob @ V per head (causal K truncation) ----------------
__global__ void __launch_bounds__(256) av_kernel(
    const float* __restrict__ prob, const float* __restrict__ v, float* __restrict__ vec)
{
    const int head = blockIdx.y;
    const int b = head / NH, n = head % NH;
    const int i0 = blockIdx.x * 64;
    const float* pr = prob + (size_t)head * S_ * S_;
    __shared__ float Ps[16][65];
    __shared__ float Vs[16][64];
    const int tid = threadIdx.x;
    const int tx = tid & 15, ty = tid >> 4;
    const int dl = tid & 15, lq = tid >> 4;
    const int vc = tid & 63, vr = tid >> 6;     // vr 0..3
    float acc[4][4];
    #pragma unroll
    for (int i = 0; i < 4; i++)
        #pragma unroll
        for (int j = 0; j < 4; j++) acc[i][j] = 0.f;

    const int kend = i0 + 64;  // prob[i, j>i] == 0
    for (int j0 = 0; j0 < kend; j0 += 16) {
        #pragma unroll
        for (int s = 0; s < 4; s++) {
            int li = lq + s * 16;
            Ps[dl][li] = pr[(size_t)(i0 + li) * S_ + j0 + dl];
        }
        #pragma unroll
        for (int s = 0; s < 4; s++) {
            int jr = vr + s * 4;
            Vs[jr][vc] = v[((size_t)((j0 + jr) * B_ + b)) * ND + n * DH + vc];
        }
        __syncthreads();
        #pragma unroll
        for (int kk = 0; kk < 16; kk++) {
            float p[4], vv[4];
            #pragma unroll
            for (int t = 0; t < 4; t++) p[t] = Ps[kk][ty * 4 + t];
            *(float4*)vv = *(const float4*)&Vs[kk][tx * 4];
            #pragma unroll
            for (int i = 0; i < 4; i++)
                #pragma unroll
                for (int j = 0; j < 4; j++)
                    acc[i][j] += p[i] * vv[j];
        }
        __syncthreads();
    }
    #pragma unroll
    for (int i = 0; i < 4; i++) {
        int gi = i0 + ty * 4 + i;
        #pragma unroll
        for (int j = 0; j < 4; j++)
            vec[((size_t)(gi * B_ + b)) * ND + n * DH + tx * 4 + j] = acc[i][j];
    }
}

// ---------------- layernorm (optional fused residual add) ----------------
__global__ void ln_kernel(const float* __restrict__ x, const float* __restrict__ res,
                          const float* __restrict__ g, const float* __restrict__ b,
                          float* __restrict__ out)
{
    __shared__ float red[256];
    const int row = blockIdx.x, tid = threadIdx.x;
    const float* xr = x + (size_t)row * D_;
    float v[4];
    float s = 0.f;
    #pragma unroll
    for (int t = 0; t < 4; t++) {
        int d = tid + t * 256;
        v[t] = xr[d];
        if (res) v[t] += res[(size_t)row * D_ + d];
        s += v[t];
    }
    red[tid] = s; __syncthreads();
    for (int o = 128; o > 0; o >>= 1) { if (tid < o) red[tid] += red[tid + o]; __syncthreads(); }
    float mean = red[0] * (1.f / D_);
    __syncthreads();
    s = 0.f;
    #pragma unroll
    for (int t = 0; t < 4; t++) { float d2 = v[t] - mean; s += d2 * d2; }
    red[tid] = s; __syncthreads();
    for (int o = 128; o > 0; o >>= 1) { if (tid < o) red[tid] += red[tid + o]; __syncthreads(); }
    float inv = rsqrtf(red[0] * (1.f / D_) + 1e-12f);
    #pragma unroll
    for (int t = 0; t < 4; t++) {
        int d = tid + t * 256;
        out[(size_t)row * D_ + d] = (v[t] - mean) * inv * g[d] + b[d];
    }
}

// ---------------- host ----------------
static float* sym_addr(const void* sym) {
    void* p = nullptr;
    cudaGetSymbolAddress(&p, sym);
    return (float*)p;
}

extern "C" void kernel_launch(void* const* d_in, const int* in_sizes, int n_in,
                              void* d_out, int out_size)
{
    (void)in_sizes; (void)n_in; (void)out_size;
    const float* h         = (const float*)d_in[0];
    const float* pos_emb   = (const float*)d_in[1];
    const float* attn_mask = (const float*)d_in[2];
    const float* seg_mat   = (const float*)d_in[3];
    const float* Wq        = (const float*)d_in[4];
    const float* Wk        = (const float*)d_in[5];
    const float* Wv        = (const float*)d_in[6];
    const float* Wo        = (const float*)d_in[7];
    const float* Wr        = (const float*)d_in[8];
    const float* rw        = (const float*)d_in[9];
    const float* rr        = (const float*)d_in[10];
    const float* rs        = (const float*)d_in[11];
    const float* se        = (const float*)d_in[12];
    const float* ln1g      = (const float*)d_in[13];
    const float* ln1b      = (const float*)d_in[14];
    const float* w1        = (const float*)d_in[15];
    const float* b1        = (const float*)d_in[16];
    const float* w2        = (const float*)d_in[17];
    const float* b2        = (const float*)d_in[18];
    const float* ln2g      = (const float*)d_in[19];
    const float* ln2b      = (const float*)d_in[20];
    float* out = (float*)d_out;

    float* gq    = sym_addr(g_q);
    float* gk    = sym_addr(g_k);
    float* gv    = sym_addr(g_v);
    float* gkr   = sym_addr(g_kr);
    float* gef   = sym_addr(g_ef);
    float* gsc   = sym_addr(g_score);
    float* gvec  = sym_addr(g_vec);
    float* gattn = sym_addr(g_attn);
    float* gx    = sym_addr(g_x);
    float* gf    = sym_addr(g_f);
    float* gf2   = sym_addr(g_f2);
    float* gbuf  = sym_addr(g_buf);

    for (int l = 0; l < 2; l++) {
        const float* cur = (l == 0) ? h : gbuf;
        float* nxt = (l == 0) ? gbuf : out;
        const size_t woff = (size_t)l * D_ * ND;

        dim3 gproj(ND / 128, SB / 128);
        gemm128<EPI_NONE, false><<<gproj, 256>>>(cur, Wq + woff, gq, SB, ND, D_, nullptr, nullptr);
        gemm128<EPI_NONE, false><<<gproj, 256>>>(cur, Wk + woff, gk, SB, ND, D_, nullptr, nullptr);
        gemm128<EPI_NONE, false><<<gproj, 256>>>(cur, Wv + woff, gv, SB, ND, D_, nullptr, nullptr);
        gemm128<EPI_NONE, false><<<dim3(ND / 128, RB / 128), 256>>>(
            pos_emb, Wr + woff, gkr, RB, ND, D_, nullptr, nullptr);

        ef_kernel<<<SB * NH / 4, 128>>>(gq, rs + l * NH * DH, se + l * 2 * NH * DH, gef);

        score_kernel<<<dim3(S_ / 64, S_ / 64, NHEADS), 256>>>(
            gq, gk, gkr, rw + l * NH * DH, rr + l * NH * DH,
            gef, seg_mat, attn_mask, gsc);

        softmax_kernel<<<dim3(S_, NHEADS), 256>>>(gsc);

        av_kernel<<<dim3(S_ / 64, NHEADS), 256>>>(gsc, gv, gvec);

        gemm128<EPI_RES, true><<<dim3(D_ / 128, SB / 128), 256>>>(
            gvec, Wo + woff, gattn, SB, D_, ND, nullptr, cur);

        ln_kernel<<<SB, 256>>>(gattn, nullptr, ln1g + l * D_, ln1b + l * D_, gx);

        gemm128<EPI_BIAS_GELU, false><<<dim3(DI_ / 128, SB / 128), 256>>>(
            gx, w1 + (size_t)l * D_ * DI_, gf, SB, DI_, D_, b1 + l * DI_, nullptr);

        gemm128<EPI_BIAS, false><<<dim3(D_ / 128, SB / 128), 256>>>(
            gf, w2 + (size_t)l * DI_ * D_, gf2, SB, D_, DI_, b2 + l * D_, nullptr);

        ln_kernel<<<SB, 256>>>(gf2, gx, ln2g + l * D_, ln2b + l * D_, nxt);
    }
}

// round 2
// speedup vs baseline: 1.1880x; 1.1880x over previous
#include <cuda_runtime.h>
#include <math.h>

#define S_   1024
#define B_   2
#define D_   1024
#define NH   16
#define DH   64
#define DI_  4096
#define R_   2048
#define SB   (S_*B_)          // 2048
#define RB   (R_*B_)          // 4096
#define ND   (NH*DH)          // 1024
#define NHEADS (B_*NH)        // 32

// ---------------- scratch (device globals; no allocation allowed) ----------------
__device__ float g_q   [SB*ND];
__device__ float g_k   [SB*ND];
__device__ float g_v   [SB*ND];
__device__ float g_kr  [RB*ND];
__device__ float g_ef  [SB*NH*2];
__device__ float g_score[(size_t)NHEADS*S_*S_];   // 128 MiB
__device__ float g_vec [SB*ND];
__device__ float g_attn[SB*ND];
__device__ float g_x   [SB*ND];
__device__ float g_f   [SB*DI_];
__device__ float g_f2  [SB*ND];
__device__ float g_buf [SB*ND];

enum { EPI_NONE = 0, EPI_BIAS = 1, EPI_BIAS_GELU = 2, EPI_RES = 3 };

__device__ __forceinline__ float gelu_f(float x) {
    return 0.5f * x * (1.0f + erff(x * 0.7071067811865476f));
}

// ---------------- tf32 helpers ----------------
__device__ __forceinline__ unsigned tf32_hi(float x) {
    unsigned r;
    asm("cvt.rna.tf32.f32 %0, %1;" : "=r"(r) : "f"(x));
    return r;
}

__device__ __forceinline__ void mma_tf32(float& c0, float& c1, float& c2, float& c3,
                                         unsigned a0, unsigned a1, unsigned a2, unsigned a3,
                                         unsigned b0, unsigned b1) {
    asm volatile(
        "mma.sync.aligned.m16n8k8.row.col.f32.tf32.tf32.f32 "
        "{%0,%1,%2,%3}, {%4,%5,%6,%7}, {%8,%9}, {%0,%1,%2,%3};\n"
        : "+f"(c0), "+f"(c1), "+f"(c2), "+f"(c3)
        : "r"(a0), "r"(a1), "r"(a2), "r"(a3), "r"(b0), "r"(b1));
}

// ---------------- tensor-core 128x128 GEMM, 3xTF32 split, NN / NT, fused epilogues ----------------
// C[M,N] = A[M,K] @ B  (B is [K,N] if !TB, [N,K] if TB)
template<int EPI, bool TB>
__global__ void __launch_bounds__(256) tgemm(
    const float* __restrict__ A, const float* __restrict__ Bm, float* __restrict__ C,
    int M, int Nn, int K, const float* __restrict__ bias, const float* __restrict__ res)
{
    __shared__ float As[16][132];   // [k][m]
    __shared__ float Bs[16][132];   // [k][n]
    const int tid = threadIdx.x;
    const int wid = tid >> 5, lane = tid & 31;
    const int m0 = blockIdx.y * 128, n0 = blockIdx.x * 128;
    const int wm = (wid >> 2) * 64;     // warp m offset (0 or 64)
    const int wn = (wid & 3) * 32;      // warp n offset (0..96)
    const int g  = lane >> 2;           // groupID 0..7
    const int tg = lane & 3;            // thread-in-group 0..3

    // loaders
    const int lm = tid >> 1, lq = (tid & 1) * 8;           // A: 128 rows x 16 k
    const int bn2 = tid >> 1, bq = (tid & 1) * 8;          // B (NT)
    const int bk = tid >> 5, bn = (tid & 31) * 4;          // B (NN)

    float acc[4][4][4];
    #pragma unroll
    for (int mt = 0; mt < 4; mt++)
        #pragma unroll
        for (int nt = 0; nt < 4; nt++)
            #pragma unroll
            for (int r = 0; r < 4; r++) acc[mt][nt][r] = 0.f;

    for (int k0 = 0; k0 < K; k0 += 16) {
        // load A tile (transpose to k-major)
        {
            float4 v0 = *(const float4*)(A + (size_t)(m0 + lm) * K + k0 + lq);
            float4 v1 = *(const float4*)(A + (size_t)(m0 + lm) * K + k0 + lq + 4);
            As[lq + 0][lm] = v0.x; As[lq + 1][lm] = v0.y;
            As[lq + 2][lm] = v0.z; As[lq + 3][lm] = v0.w;
            As[lq + 4][lm] = v1.x; As[lq + 5][lm] = v1.y;
            As[lq + 6][lm] = v1.z; As[lq + 7][lm] = v1.w;
        }
        if (TB) {
            float4 v0 = *(const float4*)(Bm + (size_t)(n0 + bn2) * K + k0 + bq);
            float4 v1 = *(const float4*)(Bm + (size_t)(n0 + bn2) * K + k0 + bq + 4);
            Bs[bq + 0][bn2] = v0.x; Bs[bq + 1][bn2] = v0.y;
            Bs[bq + 2][bn2] = v0.z; Bs[bq + 3][bn2] = v0.w;
            Bs[bq + 4][bn2] = v1.x; Bs[bq + 5][bn2] = v1.y;
            Bs[bq + 6][bn2] = v1.z; Bs[bq + 7][bn2] = v1.w;
        } else {
            *(float4*)&Bs[bk][bn]     = *(const float4*)(Bm + (size_t)(k0 + bk) * Nn + n0 + bn);
            *(float4*)&Bs[bk + 8][bn] = *(const float4*)(Bm + (size_t)(k0 + bk + 8) * Nn + n0 + bn);
        }
        __syncthreads();

        #pragma unroll
        for (int ks = 0; ks < 16; ks += 8) {
            // B fragments + split
            unsigned bh[4][2], bl[4][2];
            #pragma unroll
            for (int nt = 0; nt < 4; nt++) {
                float x0 = Bs[ks + tg][wn + nt * 8 + g];
                float x1 = Bs[ks + tg + 4][wn + nt * 8 + g];
                bh[nt][0] = tf32_hi(x0);
                bh[nt][1] = tf32_hi(x1);
                bl[nt][0] = __float_as_uint(x0 - __uint_as_float(bh[nt][0]));
                bl[nt][1] = __float_as_uint(x1 - __uint_as_float(bh[nt][1]));
            }
            #pragma unroll
            for (int mt = 0; mt < 4; mt++) {
                float a0 = As[ks + tg][wm + mt * 16 + g];
                float a1 = As[ks + tg][wm + mt * 16 + g + 8];
                float a2 = As[ks + tg + 4][wm + mt * 16 + g];
                float a3 = As[ks + tg + 4][wm + mt * 16 + g + 8];
                unsigned ah0 = tf32_hi(a0), ah1 = tf32_hi(a1), ah2 = tf32_hi(a2), ah3 = tf32_hi(a3);
                unsigned al0 = __float_as_uint(a0 - __uint_as_float(ah0));
                unsigned al1 = __float_as_uint(a1 - __uint_as_float(ah1));
                unsigned al2 = __float_as_uint(a2 - __uint_as_float(ah2));
                unsigned al3 = __float_as_uint(a3 - __uint_as_float(ah3));
                #pragma unroll
                for (int nt = 0; nt < 4; nt++) {
                    float* c = acc[mt][nt];
                    mma_tf32(c[0], c[1], c[2], c[3], al0, al1, al2, al3, bh[nt][0], bh[nt][1]);
                    mma_tf32(c[0], c[1], c[2], c[3], ah0, ah1, ah2, ah3, bl[nt][0], bl[nt][1]);
                    mma_tf32(c[0], c[1], c[2], c[3], ah0, ah1, ah2, ah3, bh[nt][0], bh[nt][1]);
                }
            }
        }
        __syncthreads();
    }

    // epilogue
    #pragma unroll
    for (int mt = 0; mt < 4; mt++) {
        int r0 = m0 + wm + mt * 16 + g;
        #pragma unroll
        for (int nt = 0; nt < 4; nt++) {
            int c0 = n0 + wn + nt * 8 + tg * 2;
            #pragma unroll
            for (int r = 0; r < 4; r++) {
                int mm = r0 + (r >> 1) * 8;
                int nn = c0 + (r & 1);
                float v = acc[mt][nt][r];
                if (EPI == EPI_BIAS || EPI == EPI_BIAS_GELU) v += bias[nn];
                if (EPI == EPI_BIAS_GELU) v = gelu_f(v);
                if (EPI == EPI_RES) v += res[(size_t)mm * Nn + nn];
                C[(size_t)mm * Nn + nn] = v;
            }
        }
    }
}

// ---------------- ef[i,b,n,s] = (q + r_s_bias) . seg_embed[s] ----------------
__global__ void ef_kernel(const float* __restrict__ q, const float* __restrict__ rs,
                          const float* __restrict__ se, float* __restrict__ ef)
{
    int w = blockIdx.x * 4 + (threadIdx.x >> 5);   // over SB*NH
    int lane = threadIdx.x & 31;
    int row = w / NH, n = w % NH;
    int d0 = lane * 2;
    const float* qp = q + (size_t)row * ND + n * DH;
    float q0 = qp[d0]     + rs[n * DH + d0];
    float q1 = qp[d0 + 1] + rs[n * DH + d0 + 1];
    float s0 = q0 * se[(0 * NH + n) * DH + d0] + q1 * se[(0 * NH + n) * DH + d0 + 1];
    float s1 = q0 * se[(1 * NH + n) * DH + d0] + q1 * se[(1 * NH + n) * DH + d0 + 1];
    #pragma unroll
    for (int off = 16; off; off >>= 1) {
        s0 += __shfl_xor_sync(0xffffffffu, s0, off);
        s1 += __shfl_xor_sync(0xffffffffu, s1, off);
    }
    if (lane == 0) { ef[w * 2] = s0; ef[w * 2 + 1] = s1; }
}

// ---------------- fused relative-attention score ----------------
// score[i,j] = ((q+rw).k[j] + (q+rr).kr[S+j-i] + seg_mat.ef) * scale - 1e30*mask
__global__ void __launch_bounds__(256) score_kernel(
    const float* __restrict__ q, const float* __restrict__ k, const float* __restrict__ kr,
    const float* __restrict__ rw, const float* __restrict__ rr,
    const float* __restrict__ ef, const float* __restrict__ seg_mat,
    const float* __restrict__ attn_mask, float* __restrict__ score)
{
    const int head = blockIdx.z;
    const int b = head / NH, n = head % NH;
    const int i0 = blockIdx.y * 64, j0 = blockIdx.x * 64;
    if (j0 > i0) return;   // fully-masked tile: never read downstream
    float* sc = score + (size_t)head * S_ * S_;
    const int tid = threadIdx.x;

    __shared__ float Qw[16][65], Qr[16][65], Kh[16][65], Krs[16][129];
    const int dl = tid & 15;
    const int lr = tid >> 4;
    const int r_base = S_ + j0 - i0 - 63;   // in [1, 961]
    const int tx = tid & 15, ty = tid >> 4;
    const int li0 = ty * 4, lj0 = tx * 4;

    float acc_ac[4][4], acc_bd[4][4];
    #pragma unroll
    for (int i = 0; i < 4; i++)
        #pragma unroll
        for (int j = 0; j < 4; j++) { acc_ac[i][j] = 0.f; acc_bd[i][j] = 0.f; }

    for (int kc = 0; kc < 4; kc++) {
        const int d0 = kc * 16;
        const float bw = rw[n * DH + d0 + dl];
        const float br = rr[n * DH + d0 + dl];
        #pragma unroll
        for (int s = 0; s < 4; s++) {
            int li = lr + s * 16;
            float qv = q[((size_t)((i0 + li) * B_ + b)) * ND + n * DH + d0 + dl];
            Qw[dl][li] = qv + bw;
            Qr[dl][li] = qv + br;
            Kh[dl][li] = k[((size_t)((j0 + li) * B_ + b)) * ND + n * DH + d0 + dl];
        }
        #pragma unroll
        for (int s = 0; s < 8; s++) {
            int lrr = lr + s * 16;
            Krs[dl][lrr] = kr[((size_t)((r_base + lrr) * B_ + b)) * ND + n * DH + d0 + dl];
        }
        __syncthreads();
        #pragma unroll
        for (int kk = 0; kk < 16; kk++) {
            float a[4], ar[4], bb[4];
            #pragma unroll
            for (int t = 0; t < 4; t++) {
                a[t]  = Qw[kk][li0 + t];
                ar[t] = Qr[kk][li0 + t];
                bb[t] = Kh[kk][lj0 + t];
            }
            #pragma unroll
            for (int i = 0; i < 4; i++)
                #pragma unroll
                for (int j = 0; j < 4; j++) {
                    acc_ac[i][j] += a[i] * bb[j];
                    acc_bd[i][j] += ar[i] * Krs[kk][lj0 + j - li0 - i + 63];
                }
        }
        __syncthreads();
    }

    const float scale = 0.125f;  // 1/sqrt(64)
    #pragma unroll
    for (int i = 0; i < 4; i++) {
        int gi = i0 + li0 + i;
        float ef0 = ef[((size_t)(gi * B_ + b) * NH + n) * 2 + 0];
        float ef1 = ef[((size_t)(gi * B_ + b) * NH + n) * 2 + 1];
        #pragma unroll
        for (int j = 0; j < 4; j++) {
            int gj = j0 + lj0 + j;
            const float* sm = seg_mat + (((size_t)gi * S_ + gj) * B_ + b) * 2;
            float msk = attn_mask[(size_t)gi * S_ + gj];
            float v = (acc_ac[i][j] + acc_bd[i][j] + sm[0] * ef0 + sm[1] * ef1) * scale
                      - 1e30f * msk;
            sc[(size_t)gi * S_ + gj] = v;
        }
    }
}

// ---------------- row softmax over valid causal prefix ----------------
__global__ void softmax_kernel(float* __restrict__ score)
{
    const int head = blockIdx.y, i = blockIdx.x;
    float* row = score + (size_t)head * S_ * S_ + (size_t)i * S_;
    const int L = ((i >> 6) + 1) << 6;   // padded to 64-tile; entries j>i are -1e30
    __shared__ float red[256];
    const int tid = threadIdx.x;
    float mx = -3.0e38f;
    for (int t = tid; t < L; t += 256) mx = fmaxf(mx, row[t]);
    red[tid] = mx; __syncthreads();
    for (int o = 128; o > 0; o >>= 1) { if (tid < o) red[tid] = fmaxf(red[tid], red[tid + o]); __syncthreads(); }
    mx = red[0]; __syncthreads();
    float s = 0.f;
    for (int t = tid; t < L; t += 256) s += expf(row[t] - mx);
    red[tid] = s; __syncthreads();
    for (int o = 128; o > 0; o >>= 1) { if (tid < o) red[tid] += red[tid + o]; __syncthreads(); }
    float inv = 1.0f / red[0];
    for (int t = tid; t < L; t += 256) row[t] = expf(row[t] - mx) * inv;
}

// ---------------- vec = prob @ V per head (causal K truncation) ----------------
__global__ void __launch_bounds__(256) av_kernel(
    const float* __restrict__ prob, const float* __restrict__ v, float* __restrict__ vec)
{
    const int head = blockIdx.y;
    const int b = head / NH, n = head % NH;
    const int i0 = blockIdx.x * 64;
    const float* pr = prob + (size_t)head * S_ * S_;
    __shared__ float Ps[16][65];
    __shared__ float Vs[16][64];
    const int tid = threadIdx.x;
    const int tx = tid & 15, ty = tid >> 4;
    const int dl = tid & 15, lq = tid >> 4;
    const int vc = tid & 63, vr = tid >> 6;     // vr 0..3
    float acc[4][4];
    #pragma unroll
    for (int i = 0; i < 4; i++)
        #pragma unroll
        for (int j = 0; j < 4; j++) acc[i][j] = 0.f;

    const int kend = i0 + 64;  // prob[i, j>i] == 0
    for (int j0 = 0; j0 < kend; j0 += 16) {
        #pragma unroll
        for (int s = 0; s < 4; s++) {
            int li = lq + s * 16;
            Ps[dl][li] = pr[(size_t)(i0 + li) * S_ + j0 + dl];
        }
        #pragma unroll
        for (int s = 0; s < 4; s++) {
            int jr = vr + s * 4;
            Vs[jr][vc] = v[((size_t)((j0 + jr) * B_ + b)) * ND + n * DH + vc];
        }
        __syncthreads();
        #pragma unroll
        for (int kk = 0; kk < 16; kk++) {
            float p[4], vv[4];
            #pragma unroll
            for (int t = 0; t < 4; t++) p[t] = Ps[kk][ty * 4 + t];
            *(float4*)vv = *(const float4*)&Vs[kk][tx * 4];
            #pragma unroll
            for (int i = 0; i < 4; i++)
                #pragma unroll
                for (int j = 0; j < 4; j++)
                    acc[i][j] += p[i] * vv[j];
        }
        __syncthreads();
    }
    #pragma unroll
    for (int i = 0; i < 4; i++) {
        int gi = i0 + ty * 4 + i;
        #pragma unroll
        for (int j = 0; j < 4; j++)
            vec[((size_t)(gi * B_ + b)) * ND + n * DH + tx * 4 + j] = acc[i][j];
    }
}

// ---------------- layernorm (optional fused residual add) ----------------
__global__ void ln_kernel(const float* __restrict__ x, const float* __restrict__ res,
                          const float* __restrict__ g, const float* __restrict__ b,
                          float* __restrict__ out)
{
    __shared__ float red[256];
    const int row = blockIdx.x, tid = threadIdx.x;
    const float* xr = x + (size_t)row * D_;
    float v[4];
    float s = 0.f;
    #pragma unroll
    for (int t = 0; t < 4; t++) {
        int d = tid + t * 256;
        v[t] = xr[d];
        if (res) v[t] += res[(size_t)row * D_ + d];
        s += v[t];
    }
    red[tid] = s; __syncthreads();
    for (int o = 128; o > 0; o >>= 1) { if (tid < o) red[tid] += red[tid + o]; __syncthreads(); }
    float mean = red[0] * (1.f / D_);
    __syncthreads();
    s = 0.f;
    #pragma unroll
    for (int t = 0; t < 4; t++) { float d2 = v[t] - mean; s += d2 * d2; }
    red[tid] = s; __syncthreads();
    for (int o = 128; o > 0; o >>= 1) { if (tid < o) red[tid] += red[tid + o]; __syncthreads(); }
    float inv = rsqrtf(red[0] * (1.f / D_) + 1e-12f);
    #pragma unroll
    for (int t = 0; t < 4; t++) {
        int d = tid + t * 256;
        out[(size_t)row * D_ + d] = (v[t] - mean) * inv * g[d] + b[d];
    }
}

// ---------------- host ----------------
static float* sym_addr(const void* sym) {
    void* p = nullptr;
    cudaGetSymbolAddress(&p, sym);
    return (float*)p;
}

extern "C" void kernel_launch(void* const* d_in, const int* in_sizes, int n_in,
                              void* d_out, int out_size)
{
    (void)in_sizes; (void)n_in; (void)out_size;
    const float* h         = (const float*)d_in[0];
    const float* pos_emb   = (const float*)d_in[1];
    const float* attn_mask = (const float*)d_in[2];
    const float* seg_mat   = (const float*)d_in[3];
    const float* Wq        = (const float*)d_in[4];
    const float* Wk        = (const float*)d_in[5];
    const float* Wv        = (const float*)d_in[6];
    const float* Wo        = (const float*)d_in[7];
    const float* Wr        = (const float*)d_in[8];
    const float* rw        = (const float*)d_in[9];
    const float* rr        = (const float*)d_in[10];
    const float* rs        = (const float*)d_in[11];
    const float* se        = (const float*)d_in[12];
    const float* ln1g      = (const float*)d_in[13];
    const float* ln1b      = (const float*)d_in[14];
    const float* w1        = (const float*)d_in[15];
    const float* b1        = (const float*)d_in[16];
    const float* w2        = (const float*)d_in[17];
    const float* b2        = (const float*)d_in[18];
    const float* ln2g      = (const float*)d_in[19];
    const float* ln2b      = (const float*)d_in[20];
    float* out = (float*)d_out;

    float* gq    = sym_addr(g_q);
    float* gk    = sym_addr(g_k);
    float* gv    = sym_addr(g_v);
    float* gkr   = sym_addr(g_kr);
    float* gef   = sym_addr(g_ef);
    float* gsc   = sym_addr(g_score);
    float* gvec  = sym_addr(g_vec);
    float* gattn = sym_addr(g_attn);
    float* gx    = sym_addr(g_x);
    float* gf    = sym_addr(g_f);
    float* gf2   = sym_addr(g_f2);
    float* gbuf  = sym_addr(g_buf);

    for (int l = 0; l < 2; l++) {
        const float* cur = (l == 0) ? h : gbuf;
        float* nxt = (l == 0) ? gbuf : out;
        const size_t woff = (size_t)l * D_ * ND;

        dim3 gproj(ND / 128, SB / 128);
        tgemm<EPI_NONE, false><<<gproj, 256>>>(cur, Wq + woff, gq, SB, ND, D_, nullptr, nullptr);
        tgemm<EPI_NONE, false><<<gproj, 256>>>(cur, Wk + woff, gk, SB, ND, D_, nullptr, nullptr);
        tgemm<EPI_NONE, false><<<gproj, 256>>>(cur, Wv + woff, gv, SB, ND, D_, nullptr, nullptr);
        tgemm<EPI_NONE, false><<<dim3(ND / 128, RB / 128), 256>>>(
            pos_emb, Wr + woff, gkr, RB, ND, D_, nullptr, nullptr);

        ef_kernel<<<SB * NH / 4, 128>>>(gq, rs + l * NH * DH, se + l * 2 * NH * DH, gef);

        score_kernel<<<dim3(S_ / 64, S_ / 64, NHEADS), 256>>>(
            gq, gk, gkr, rw + l * NH * DH, rr + l * NH * DH,
            gef, seg_mat, attn_mask, gsc);

        softmax_kernel<<<dim3(S_, NHEADS), 256>>>(gsc);

        av_kernel<<<dim3(S_ / 64, NHEADS), 256>>>(gsc, gv, gvec);

        tgemm<EPI_RES, true><<<dim3(D_ / 128, SB / 128), 256>>>(
            gvec, Wo + woff, gattn, SB, D_, ND, nullptr, cur);

        ln_kernel<<<SB, 256>>>(gattn, nullptr, ln1g + l * D_, ln1b + l * D_, gx);

        tgemm<EPI_BIAS_GELU, false><<<dim3(DI_ / 128, SB / 128), 256>>>(
            gx, w1 + (size_t)l * D_ * DI_, gf, SB, DI_, D_, b1 + l * DI_, nullptr);

        tgemm<EPI_BIAS, false><<<dim3(D_ / 128, SB / 128), 256>>>(
            gf, w2 + (size_t)l * DI_ * D_, gf2, SB, D_, DI_, b2 + l * D_, nullptr);

        ln_kernel<<<SB, 256>>>(gf2, gx, ln2g + l * D_, ln2b + l * D_, nxt);
    }
}

// round 3
// speedup vs baseline: 1.8106x; 1.5241x over previous
#include <cuda_runtime.h>
#include <math.h>

#define S_   1024
#define B_   2
#define D_   1024
#define NH   16
#define DH   64
#define DI_  4096
#define R_   2048
#define SB   (S_*B_)          // 2048
#define RB   (R_*B_)          // 4096
#define ND   (NH*DH)          // 1024
#define NHEADS (B_*NH)        // 32

// ---------------- scratch (device globals; no allocation allowed) ----------------
__device__ float g_q   [SB*ND];
__device__ float g_k   [SB*ND];
__device__ float g_v   [SB*ND];
__device__ float g_kr  [RB*ND];
__device__ float g_ef  [SB*NH*2];
__device__ float g_score[(size_t)NHEADS*S_*S_];   // 128 MiB
__device__ float g_vec [SB*ND];
__device__ float g_attn[SB*ND];
__device__ float g_x   [SB*ND];
__device__ float g_f   [SB*DI_];
__device__ float g_f2  [SB*ND];
__device__ float g_buf [SB*ND];

enum { EPI_NONE = 0, EPI_BIAS = 1, EPI_BIAS_GELU = 2, EPI_RES = 3 };

__device__ __forceinline__ float gelu_f(float x) {
    return 0.5f * x * (1.0f + erff(x * 0.7071067811865476f));
}

// ---------------- bf16 split helpers ----------------
// pack (x0 -> low half, x1 -> high half) hi terms; residuals likewise
__device__ __forceinline__ void split2(float x0, float x1, unsigned& hi, unsigned& lo) {
    unsigned h;
    asm("cvt.rn.bf16x2.f32 %0, %1, %2;" : "=r"(h) : "f"(x1), "f"(x0));
    float h0 = __uint_as_float(h << 16);
    float h1 = __uint_as_float(h & 0xffff0000u);
    float r0 = x0 - h0;
    float r1 = x1 - h1;
    unsigned l;
    asm("cvt.rn.bf16x2.f32 %0, %1, %2;" : "=r"(l) : "f"(r1), "f"(r0));
    hi = h; lo = l;
}

__device__ __forceinline__ void mma_bf16(float* c,
    unsigned a0, unsigned a1, unsigned a2, unsigned a3, unsigned b0, unsigned b1) {
    asm volatile(
        "mma.sync.aligned.m16n8k16.row.col.f32.bf16.bf16.f32 "
        "{%0,%1,%2,%3}, {%4,%5,%6,%7}, {%8,%9}, {%0,%1,%2,%3};\n"
        : "+f"(c[0]), "+f"(c[1]), "+f"(c[2]), "+f"(c[3])
        : "r"(a0), "r"(a1), "r"(a2), "r"(a3), "r"(b0), "r"(b1));
}

// ---------------- tensor-core 128x128 GEMM, bf16 split, NN / NT, fused epilogues ----------------
// C[M,N] = A[M,K] @ B  (B is [K,N] if !TB, [N,K] if TB)
// smem layout: [stage][kpair 0..7][col 0..127], stride 136 (mod 32 == 8 -> conflict-free frags)
template<int EPI, bool TB>
__global__ void __launch_bounds__(256) tgemm(
    const float* __restrict__ A, const float* __restrict__ Bm, float* __restrict__ C,
    int M, int Nn, int K, const float* __restrict__ bias, const float* __restrict__ res)
{
    __shared__ unsigned Ah[2][8][136], Al[2][8][136];
    __shared__ unsigned Bh[2][8][136], Bl[2][8][136];
    const int tid = threadIdx.x;
    const int wid = tid >> 5, lane = tid & 31;
    const int m0 = blockIdx.y * 128, n0 = blockIdx.x * 128;
    const int wm = (wid >> 2) * 64;     // warp m offset (0 or 64)
    const int wn = (wid & 3) * 32;      // warp n offset (0..96)
    const int g  = lane >> 2;           // 0..7
    const int tg = lane & 3;            // 0..3

    // A loader (also B loader when TB): row = base + (tid>>1), k offset (tid&1)*8
    const int lm = tid >> 1, lq = (tid & 1) * 8;
    // B NN loader: k rows 2*bk, 2*bk+1 ; cols bn..bn+3
    const int bk = tid >> 5, bn = (tid & 31) * 4;

    float acc[4][4][4];
    #pragma unroll
    for (int mt = 0; mt < 4; mt++)
        #pragma unroll
        for (int nt = 0; nt < 4; nt++)
            #pragma unroll
            for (int r = 0; r < 4; r++) acc[mt][nt][r] = 0.f;

    float a_st[8], b_st[8];

    auto load_slab = [&](int k0) {
        *(float4*)(a_st)     = *(const float4*)(A + (size_t)(m0 + lm) * K + k0 + lq);
        *(float4*)(a_st + 4) = *(const float4*)(A + (size_t)(m0 + lm) * K + k0 + lq + 4);
        if (TB) {
            *(float4*)(b_st)     = *(const float4*)(Bm + (size_t)(n0 + lm) * K + k0 + lq);
            *(float4*)(b_st + 4) = *(const float4*)(Bm + (size_t)(n0 + lm) * K + k0 + lq + 4);
        } else {
            *(float4*)(b_st)     = *(const float4*)(Bm + (size_t)(k0 + 2 * bk) * Nn + n0 + bn);
            *(float4*)(b_st + 4) = *(const float4*)(Bm + (size_t)(k0 + 2 * bk + 1) * Nn + n0 + bn);
        }
    };

    auto store_slab = [&](int s) {
        #pragma unroll
        for (int j = 0; j < 4; j++) {
            unsigned hi, lo;
            split2(a_st[2 * j], a_st[2 * j + 1], hi, lo);
            Ah[s][(lq >> 1) + j][lm] = hi;
            Al[s][(lq >> 1) + j][lm] = lo;
        }
        if (TB) {
            #pragma unroll
            for (int j = 0; j < 4; j++) {
                unsigned hi, lo;
                split2(b_st[2 * j], b_st[2 * j + 1], hi, lo);
                Bh[s][(lq >> 1) + j][lm] = hi;
                Bl[s][(lq >> 1) + j][lm] = lo;
            }
        } else {
            #pragma unroll
            for (int j = 0; j < 4; j++) {
                unsigned hi, lo;
                split2(b_st[j], b_st[4 + j], hi, lo);   // pair (k=2bk, k=2bk+1) at col bn+j
                Bh[s][bk][bn + j] = hi;
                Bl[s][bk][bn + j] = lo;
            }
        }
    };

    auto compute = [&](int s) {
        unsigned bh0[4], bh1[4], bl0[4], bl1[4];
        #pragma unroll
        for (int nt = 0; nt < 4; nt++) {
            int c = wn + nt * 8 + g;
            bh0[nt] = Bh[s][tg][c];     bh1[nt] = Bh[s][tg + 4][c];
            bl0[nt] = Bl[s][tg][c];     bl1[nt] = Bl[s][tg + 4][c];
        }
        #pragma unroll
        for (int mt = 0; mt < 4; mt++) {
            int r0c = wm + mt * 16 + g;
            unsigned ah0 = Ah[s][tg][r0c],     ah1 = Ah[s][tg][r0c + 8];
            unsigned ah2 = Ah[s][tg + 4][r0c], ah3 = Ah[s][tg + 4][r0c + 8];
            unsigned al0 = Al[s][tg][r0c],     al1 = Al[s][tg][r0c + 8];
            unsigned al2 = Al[s][tg + 4][r0c], al3 = Al[s][tg + 4][r0c + 8];
            #pragma unroll
            for (int nt = 0; nt < 4; nt++) {
                float* c = acc[mt][nt];
                mma_bf16(c, ah0, ah1, ah2, ah3, bh0[nt], bh1[nt]);
                mma_bf16(c, ah0, ah1, ah2, ah3, bl0[nt], bl1[nt]);
                mma_bf16(c, al0, al1, al2, al3, bh0[nt], bh1[nt]);
            }
        }
    };

    const int nslab = K >> 4;
    load_slab(0);
    store_slab(0);
    __syncthreads();
    for (int kt = 0; kt < nslab; kt++) {
        if (kt + 1 < nslab) load_slab((kt + 1) << 4);
        compute(kt & 1);
        if (kt + 1 < nslab) store_slab((kt + 1) & 1);
        __syncthreads();
    }

    // epilogue
    #pragma unroll
    for (int mt = 0; mt < 4; mt++) {
        int r0 = m0 + wm + mt * 16 + g;
        #pragma unroll
        for (int nt = 0; nt < 4; nt++) {
            int c0 = n0 + wn + nt * 8 + tg * 2;
            #pragma unroll
            for (int r = 0; r < 4; r++) {
                int mm = r0 + (r >> 1) * 8;
                int nn = c0 + (r & 1);
                float v = acc[mt][nt][r];
                if (EPI == EPI_BIAS || EPI == EPI_BIAS_GELU) v += bias[nn];
                if (EPI == EPI_BIAS_GELU) v = gelu_f(v);
                if (EPI == EPI_RES) v += res[(size_t)mm * Nn + nn];
                C[(size_t)mm * Nn + nn] = v;
            }
        }
    }
}

// ---------------- ef[i,b,n,s] = (q + r_s_bias) . seg_embed[s] ----------------
__global__ void ef_kernel(const float* __restrict__ q, const float* __restrict__ rs,
                          const float* __restrict__ se, float* __restrict__ ef)
{
    int w = blockIdx.x * 4 + (threadIdx.x >> 5);   // over SB*NH
    int lane = threadIdx.x & 31;
    int row = w / NH, n = w % NH;
    int d0 = lane * 2;
    const float* qp = q + (size_t)row * ND + n * DH;
    float q0 = qp[d0]     + rs[n * DH + d0];
    float q1 = qp[d0 + 1] + rs[n * DH + d0 + 1];
    float s0 = q0 * se[(0 * NH + n) * DH + d0] + q1 * se[(0 * NH + n) * DH + d0 + 1];
    float s1 = q0 * se[(1 * NH + n) * DH + d0] + q1 * se[(1 * NH + n) * DH + d0 + 1];
    #pragma unroll
    for (int off = 16; off; off >>= 1) {
        s0 += __shfl_xor_sync(0xffffffffu, s0, off);
        s1 += __shfl_xor_sync(0xffffffffu, s1, off);
    }
    if (lane == 0) { ef[w * 2] = s0; ef[w * 2 + 1] = s1; }
}

// ---------------- fused relative-attention score ----------------
// score[i,j] = ((q+rw).k[j] + (q+rr).kr[S+j-i] + seg_mat.ef) * scale - 1e30*mask
__global__ void __launch_bounds__(256) score_kernel(
    const float* __restrict__ q, const float* __restrict__ k, const float* __restrict__ kr,
    const float* __restrict__ rw, const float* __restrict__ rr,
    const float* __restrict__ ef, const float* __restrict__ seg_mat,
    const float* __restrict__ attn_mask, float* __restrict__ score)
{
    const int head = blockIdx.z;
    const int b = head / NH, n = head % NH;
    const int i0 = blockIdx.y * 64, j0 = blockIdx.x * 64;
    if (j0 > i0) return;   // fully-masked tile: never read downstream
    float* sc = score + (size_t)head * S_ * S_;
    const int tid = threadIdx.x;

    __shared__ float Qw[16][65], Qr[16][65], Kh[16][65], Krs[16][129];
    const int dl = tid & 15;
    const int lr = tid >> 4;
    const int r_base = S_ + j0 - i0 - 63;   // in [1, 961]
    const int tx = tid & 15, ty = tid >> 4;
    const int li0 = ty * 4, lj0 = tx * 4;

    float acc_ac[4][4], acc_bd[4][4];
    #pragma unroll
    for (int i = 0; i < 4; i++)
        #pragma unroll
        for (int j = 0; j < 4; j++) { acc_ac[i][j] = 0.f; acc_bd[i][j] = 0.f; }

    for (int kc = 0; kc < 4; kc++) {
        const int d0 = kc * 16;
        const float bw = rw[n * DH + d0 + dl];
        const float br = rr[n * DH + d0 + dl];
        #pragma unroll
        for (int s = 0; s < 4; s++) {
            int li = lr + s * 16;
            float qv = q[((size_t)((i0 + li) * B_ + b)) * ND + n * DH + d0 + dl];
            Qw[dl][li] = qv + bw;
            Qr[dl][li] = qv + br;
            Kh[dl][li] = k[((size_t)((j0 + li) * B_ + b)) * ND + n * DH + d0 + dl];
        }
        #pragma unroll
        for (int s = 0; s < 8; s++) {
            int lrr = lr + s * 16;
            Krs[dl][lrr] = kr[((size_t)((r_base + lrr) * B_ + b)) * ND + n * DH + d0 + dl];
        }
        __syncthreads();
        #pragma unroll
        for (int kk = 0; kk < 16; kk++) {
            float a[4], ar[4], bb[4];
            #pragma unroll
            for (int t = 0; t < 4; t++) {
                a[t]  = Qw[kk][li0 + t];
                ar[t] = Qr[kk][li0 + t];
                bb[t] = Kh[kk][lj0 + t];
            }
            #pragma unroll
            for (int i = 0; i < 4; i++)
                #pragma unroll
                for (int j = 0; j < 4; j++) {
                    acc_ac[i][j] += a[i] * bb[j];
                    acc_bd[i][j] += ar[i] * Krs[kk][lj0 + j - li0 - i + 63];
                }
        }
        __syncthreads();
    }

    const float scale = 0.125f;  // 1/sqrt(64)
    #pragma unroll
    for (int i = 0; i < 4; i++) {
        int gi = i0 + li0 + i;
        float ef0 = ef[((size_t)(gi * B_ + b) * NH + n) * 2 + 0];
        float ef1 = ef[((size_t)(gi * B_ + b) * NH + n) * 2 + 1];
        #pragma unroll
        for (int j = 0; j < 4; j++) {
            int gj = j0 + lj0 + j;
            const float* sm = seg_mat + (((size_t)gi * S_ + gj) * B_ + b) * 2;
            float msk = attn_mask[(size_t)gi * S_ + gj];
            float v = (acc_ac[i][j] + acc_bd[i][j] + sm[0] * ef0 + sm[1] * ef1) * scale
                      - 1e30f * msk;
            sc[(size_t)gi * S_ + gj] = v;
        }
    }
}

// ---------------- row softmax over valid causal prefix ----------------
__global__ void softmax_kernel(float* __restrict__ score)
{
    const int head = blockIdx.y, i = blockIdx.x;
    float* row = score + (size_t)head * S_ * S_ + (size_t)i * S_;
    const int L = ((i >> 6) + 1) << 6;   // padded to 64-tile; entries j>i are -1e30
    __shared__ float red[256];
    const int tid = threadIdx.x;
    float v[4];
    float mx = -3.0e38f;
    #pragma unroll
    for (int t = 0; t < 4; t++) {
        int idx = tid + t * 256;
        v[t] = (idx < L) ? row[idx] : -3.0e38f;
        mx = fmaxf(mx, v[t]);
    }
    red[tid] = mx; __syncthreads();
    for (int o = 128; o > 0; o >>= 1) { if (tid < o) red[tid] = fmaxf(red[tid], red[tid + o]); __syncthreads(); }
    mx = red[0]; __syncthreads();
    float s = 0.f;
    #pragma unroll
    for (int t = 0; t < 4; t++) { v[t] = expf(v[t] - mx); s += v[t]; }
    red[tid] = s; __syncthreads();
    for (int o = 128; o > 0; o >>= 1) { if (tid < o) red[tid] += red[tid + o]; __syncthreads(); }
    float inv = 1.0f / red[0];
    #pragma unroll
    for (int t = 0; t < 4; t++) {
        int idx = tid + t * 256;
        if (idx < L) row[idx] = v[t] * inv;
    }
}

// ---------------- vec = prob @ V per head (causal K truncation) ----------------
__global__ void __launch_bounds__(256) av_kernel(
    const float* __restrict__ prob, const float* __restrict__ v, float* __restrict__ vec)
{
    const int head = blockIdx.y;
    const int b = head / NH, n = head % NH;
    const int i0 = blockIdx.x * 64;
    const float* pr = prob + (size_t)head * S_ * S_;
    __shared__ float Ps[16][65];
    __shared__ float Vs[16][64];
    const int tid = threadIdx.x;
    const int tx = tid & 15, ty = tid >> 4;
    const int dl = tid & 15, lq = tid >> 4;
    const int vc = tid & 63, vr = tid >> 6;     // vr 0..3
    float acc[4][4];
    #pragma unroll
    for (int i = 0; i < 4; i++)
        #pragma unroll
        for (int j = 0; j < 4; j++) acc[i][j] = 0.f;

    const int kend = i0 + 64;  // prob[i, j>i] == 0
    for (int j0 = 0; j0 < kend; j0 += 16) {
        #pragma unroll
        for (int s = 0; s < 4; s++) {
            int li = lq + s * 16;
            Ps[dl][li] = pr[(size_t)(i0 + li) * S_ + j0 + dl];
        }
        #pragma unroll
        for (int s = 0; s < 4; s++) {
            int jr = vr + s * 4;
            Vs[jr][vc] = v[((size_t)((j0 + jr) * B_ + b)) * ND + n * DH + vc];
        }
        __syncthreads();
        #pragma unroll
        for (int kk = 0; kk < 16; kk++) {
            float p[4], vv[4];
            #pragma unroll
            for (int t = 0; t < 4; t++) p[t] = Ps[kk][ty * 4 + t];
            *(float4*)vv = *(const float4*)&Vs[kk][tx * 4];
            #pragma unroll
            for (int i = 0; i < 4; i++)
                #pragma unroll
                for (int j = 0; j < 4; j++)
                    acc[i][j] += p[i] * vv[j];
        }
        __syncthreads();
    }
    #pragma unroll
    for (int i = 0; i < 4; i++) {
        int gi = i0 + ty * 4 + i;
        #pragma unroll
        for (int j = 0; j < 4; j++)
            vec[((size_t)(gi * B_ + b)) * ND + n * DH + tx * 4 + j] = acc[i][j];
    }
}

// ---------------- layernorm (optional fused residual add) ----------------
__global__ void ln_kernel(const float* __restrict__ x, const float* __restrict__ res,
                          const float* __restrict__ g, const float* __restrict__ b,
                          float* __restrict__ out)
{
    __shared__ float red[256];
    const int row = blockIdx.x, tid = threadIdx.x;
    const float* xr = x + (size_t)row * D_;
    float v[4];
    float s = 0.f;
    #pragma unroll
    for (int t = 0; t < 4; t++) {
        int d = tid + t * 256;
        v[t] = xr[d];
        if (res) v[t] += res[(size_t)row * D_ + d];
        s += v[t];
    }
    red[tid] = s; __syncthreads();
    for (int o = 128; o > 0; o >>= 1) { if (tid < o) red[tid] += red[tid + o]; __syncthreads(); }
    float mean = red[0] * (1.f / D_);
    __syncthreads();
    s = 0.f;
    #pragma unroll
    for (int t = 0; t < 4; t++) { float d2 = v[t] - mean; s += d2 * d2; }
    red[tid] = s; __syncthreads();
    for (int o = 128; o > 0; o >>= 1) { if (tid < o) red[tid] += red[tid + o]; __syncthreads(); }
    float inv = rsqrtf(red[0] * (1.f / D_) + 1e-12f);
    #pragma unroll
    for (int t = 0; t < 4; t++) {
        int d = tid + t * 256;
        out[(size_t)row * D_ + d] = (v[t] - mean) * inv * g[d] + b[d];
    }
}

// ---------------- host ----------------
static float* sym_addr(const void* sym) {
    void* p = nullptr;
    cudaGetSymbolAddress(&p, sym);
    return (float*)p;
}

extern "C" void kernel_launch(void* const* d_in, const int* in_sizes, int n_in,
                              void* d_out, int out_size)
{
    (void)in_sizes; (void)n_in; (void)out_size;
    const float* h         = (const float*)d_in[0];
    const float* pos_emb   = (const float*)d_in[1];
    const float* attn_mask = (const float*)d_in[2];
    const float* seg_mat   = (const float*)d_in[3];
    const float* Wq        = (const float*)d_in[4];
    const float* Wk        = (const float*)d_in[5];
    const float* Wv        = (const float*)d_in[6];
    const float* Wo        = (const float*)d_in[7];
    const float* Wr        = (const float*)d_in[8];
    const float* rw        = (const float*)d_in[9];
    const float* rr        = (const float*)d_in[10];
    const float* rs        = (const float*)d_in[11];
    const float* se        = (const float*)d_in[12];
    const float* ln1g      = (const float*)d_in[13];
    const float* ln1b      = (const float*)d_in[14];
    const float* w1        = (const float*)d_in[15];
    const float* b1        = (const float*)d_in[16];
    const float* w2        = (const float*)d_in[17];
    const float* b2        = (const float*)d_in[18];
    const float* ln2g      = (const float*)d_in[19];
    const float* ln2b      = (const float*)d_in[20];
    float* out = (float*)d_out;

    float* gq    = sym_addr(g_q);
    float* gk    = sym_addr(g_k);
    float* gv    = sym_addr(g_v);
    float* gkr   = sym_addr(g_kr);
    float* gef   = sym_addr(g_ef);
    float* gsc   = sym_addr(g_score);
    float* gvec  = sym_addr(g_vec);
    float* gattn = sym_addr(g_attn);
    float* gx    = sym_addr(g_x);
    float* gf    = sym_addr(g_f);
    float* gf2   = sym_addr(g_f2);
    float* gbuf  = sym_addr(g_buf);

    for (int l = 0; l < 2; l++) {
        const float* cur = (l == 0) ? h : gbuf;
        float* nxt = (l == 0) ? gbuf : out;
        const size_t woff = (size_t)l * D_ * ND;

        dim3 gproj(ND / 128, SB / 128);
        tgemm<EPI_NONE, false><<<gproj, 256>>>(cur, Wq + woff, gq, SB, ND, D_, nullptr, nullptr);
        tgemm<EPI_NONE, false><<<gproj, 256>>>(cur, Wk + woff, gk, SB, ND, D_, nullptr, nullptr);
        tgemm<EPI_NONE, false><<<gproj, 256>>>(cur, Wv + woff, gv, SB, ND, D_, nullptr, nullptr);
        tgemm<EPI_NONE, false><<<dim3(ND / 128, RB / 128), 256>>>(
            pos_emb, Wr + woff, gkr, RB, ND, D_, nullptr, nullptr);

        ef_kernel<<<SB * NH / 4, 128>>>(gq, rs + l * NH * DH, se + l * 2 * NH * DH, gef);

        score_kernel<<<dim3(S_ / 64, S_ / 64, NHEADS), 256>>>(
            gq, gk, gkr, rw + l * NH * DH, rr + l * NH * DH,
            gef, seg_mat, attn_mask, gsc);

        softmax_kernel<<<dim3(S_, NHEADS), 256>>>(gsc);

        av_kernel<<<dim3(S_ / 64, NHEADS), 256>>>(gsc, gv, gvec);

        tgemm<EPI_RES, true><<<dim3(D_ / 128, SB / 128), 256>>>(
            gvec, Wo + woff, gattn, SB, D_, ND, nullptr, cur);

        ln_kernel<<<SB, 256>>>(gattn, nullptr, ln1g + l * D_, ln1b + l * D_, gx);

        tgemm<EPI_BIAS_GELU, false><<<dim3(DI_ / 128, SB / 128), 256>>>(
            gx, w1 + (size_t)l * D_ * DI_, gf, SB, DI_, D_, b1 + l * DI_, nullptr);

        tgemm<EPI_BIAS, false><<<dim3(D_ / 128, SB / 128), 256>>>(
            gf, w2 + (size_t)l * DI_ * D_, gf2, SB, D_, DI_, b2 + l * D_, nullptr);

        ln_kernel<<<SB, 256>>>(gf2, gx, ln2g + l * D_, ln2b + l * D_, nxt);
    }
}

// round 4
// speedup vs baseline: 1.9169x; 1.0587x over previous
#include <cuda_runtime.h>
#include <math.h>

#define S_   1024
#define B_   2
#define D_   1024
#define NH   16
#define DH   64
#define DI_  4096
#define R_   2048
#define SB   (S_*B_)          // 2048
#define RB   (R_*B_)          // 4096
#define ND   (NH*DH)          // 1024
#define NHEADS (B_*NH)        // 32

// ---------------- scratch (device globals; no allocation allowed) ----------------
__device__ float g_q   [SB*ND];
__device__ float g_k   [SB*ND];
__device__ float g_v   [SB*ND];
__device__ float g_kr  [RB*ND];
__device__ float g_ef  [SB*NH*2];
__device__ float g_score[(size_t)NHEADS*S_*S_];   // 128 MiB
__device__ float g_vec [SB*ND];
__device__ float g_attn[SB*ND];
__device__ float g_x   [SB*ND];
__device__ float g_f   [SB*DI_];
__device__ float g_f2  [SB*ND];
__device__ float g_buf [SB*ND];

enum { EPI_NONE = 0, EPI_BIAS = 1, EPI_BIAS_GELU = 2, EPI_RES = 3 };

__device__ __forceinline__ float gelu_f(float x) {
    return 0.5f * x * (1.0f + erff(x * 0.7071067811865476f));
}

// ---------------- bf16 split helpers ----------------
__device__ __forceinline__ void split2(float x0, float x1, unsigned& hi, unsigned& lo) {
    unsigned h;
    asm("cvt.rn.bf16x2.f32 %0, %1, %2;" : "=r"(h) : "f"(x1), "f"(x0));
    float h0 = __uint_as_float(h << 16);
    float h1 = __uint_as_float(h & 0xffff0000u);
    float r0 = x0 - h0;
    float r1 = x1 - h1;
    unsigned l;
    asm("cvt.rn.bf16x2.f32 %0, %1, %2;" : "=r"(l) : "f"(r1), "f"(r0));
    hi = h; lo = l;
}

__device__ __forceinline__ void mma_bf16(float* c,
    unsigned a0, unsigned a1, unsigned a2, unsigned a3, unsigned b0, unsigned b1) {
    asm volatile(
        "mma.sync.aligned.m16n8k16.row.col.f32.bf16.bf16.f32 "
        "{%0,%1,%2,%3}, {%4,%5,%6,%7}, {%8,%9}, {%0,%1,%2,%3};\n"
        : "+f"(c[0]), "+f"(c[1]), "+f"(c[2]), "+f"(c[3])
        : "r"(a0), "r"(a1), "r"(a2), "r"(a3), "r"(b0), "r"(b1));
}

// ---------------- tensor-core 128x128 GEMM body, bf16 split, NN / NT ----------------
template<int EPI, bool TB>
__device__ __forceinline__ void tgemm_body(
    const float* __restrict__ A, const float* __restrict__ Bm, float* __restrict__ C,
    int M, int Nn, int K, const float* __restrict__ bias, const float* __restrict__ res,
    int m0, int n0)
{
    __shared__ unsigned Ah[2][8][136], Al[2][8][136];
    __shared__ unsigned Bh[2][8][136], Bl[2][8][136];
    const int tid = threadIdx.x;
    const int wid = tid >> 5, lane = tid & 31;
    const int wm = (wid >> 2) * 64;     // warp m offset (0 or 64)
    const int wn = (wid & 3) * 32;      // warp n offset (0..96)
    const int g  = lane >> 2;           // 0..7
    const int tg = lane & 3;            // 0..3

    const int lm = tid >> 1, lq = (tid & 1) * 8;
    const int bk = tid >> 5, bn = (tid & 31) * 4;

    float acc[4][4][4];
    #pragma unroll
    for (int mt = 0; mt < 4; mt++)
        #pragma unroll
        for (int nt = 0; nt < 4; nt++)
            #pragma unroll
            for (int r = 0; r < 4; r++) acc[mt][nt][r] = 0.f;

    float a_st[8], b_st[8];

    auto load_slab = [&](int k0) {
        *(float4*)(a_st)     = *(const float4*)(A + (size_t)(m0 + lm) * K + k0 + lq);
        *(float4*)(a_st + 4) = *(const float4*)(A + (size_t)(m0 + lm) * K + k0 + lq + 4);
        if (TB) {
            *(float4*)(b_st)     = *(const float4*)(Bm + (size_t)(n0 + lm) * K + k0 + lq);
            *(float4*)(b_st + 4) = *(const float4*)(Bm + (size_t)(n0 + lm) * K + k0 + lq + 4);
        } else {
            *(float4*)(b_st)     = *(const float4*)(Bm + (size_t)(k0 + 2 * bk) * Nn + n0 + bn);
            *(float4*)(b_st + 4) = *(const float4*)(Bm + (size_t)(k0 + 2 * bk + 1) * Nn + n0 + bn);
        }
    };

    auto store_slab = [&](int s) {
        #pragma unroll
        for (int j = 0; j < 4; j++) {
            unsigned hi, lo;
            split2(a_st[2 * j], a_st[2 * j + 1], hi, lo);
            Ah[s][(lq >> 1) + j][lm] = hi;
            Al[s][(lq >> 1) + j][lm] = lo;
        }
        if (TB) {
            #pragma unroll
            for (int j = 0; j < 4; j++) {
                unsigned hi, lo;
                split2(b_st[2 * j], b_st[2 * j + 1], hi, lo);
                Bh[s][(lq >> 1) + j][lm] = hi;
                Bl[s][(lq >> 1) + j][lm] = lo;
            }
        } else {
            #pragma unroll
            for (int j = 0; j < 4; j++) {
                unsigned hi, lo;
                split2(b_st[j], b_st[4 + j], hi, lo);
                Bh[s][bk][bn + j] = hi;
                Bl[s][bk][bn + j] = lo;
            }
        }
    };

    auto compute = [&](int s) {
        unsigned bh0[4], bh1[4], bl0[4], bl1[4];
        #pragma unroll
        for (int nt = 0; nt < 4; nt++) {
            int c = wn + nt * 8 + g;
            bh0[nt] = Bh[s][tg][c];     bh1[nt] = Bh[s][tg + 4][c];
            bl0[nt] = Bl[s][tg][c];     bl1[nt] = Bl[s][tg + 4][c];
        }
        #pragma unroll
        for (int mt = 0; mt < 4; mt++) {
            int r0c = wm + mt * 16 + g;
            unsigned ah0 = Ah[s][tg][r0c],     ah1 = Ah[s][tg][r0c + 8];
            unsigned ah2 = Ah[s][tg + 4][r0c], ah3 = Ah[s][tg + 4][r0c + 8];
            unsigned al0 = Al[s][tg][r0c],     al1 = Al[s][tg][r0c + 8];
            unsigned al2 = Al[s][tg + 4][r0c], al3 = Al[s][tg + 4][r0c + 8];
            #pragma unroll
            for (int nt = 0; nt < 4; nt++) {
                float* c = acc[mt][nt];
                mma_bf16(c, ah0, ah1, ah2, ah3, bh0[nt], bh1[nt]);
                mma_bf16(c, ah0, ah1, ah2, ah3, bl0[nt], bl1[nt]);
                mma_bf16(c, al0, al1, al2, al3, bh0[nt], bh1[nt]);
            }
        }
    };

    const int nslab = K >> 4;
    load_slab(0);
    store_slab(0);
    __syncthreads();
    for (int kt = 0; kt < nslab; kt++) {
        if (kt + 1 < nslab) load_slab((kt + 1) << 4);
        compute(kt & 1);
        if (kt + 1 < nslab) store_slab((kt + 1) & 1);
        __syncthreads();
    }

    #pragma unroll
    for (int mt = 0; mt < 4; mt++) {
        int r0 = m0 + wm + mt * 16 + g;
        #pragma unroll
        for (int nt = 0; nt < 4; nt++) {
            int c0 = n0 + wn + nt * 8 + tg * 2;
            #pragma unroll
            for (int r = 0; r < 4; r++) {
                int mm = r0 + (r >> 1) * 8;
                int nn = c0 + (r & 1);
                float v = acc[mt][nt][r];
                if (EPI == EPI_BIAS || EPI == EPI_BIAS_GELU) v += bias[nn];
                if (EPI == EPI_BIAS_GELU) v = gelu_f(v);
                if (EPI == EPI_RES) v += res[(size_t)mm * Nn + nn];
                C[(size_t)mm * Nn + nn] = v;
            }
        }
    }
}

template<int EPI, bool TB>
__global__ void __launch_bounds__(256, 2) tgemm(
    const float* __restrict__ A, const float* __restrict__ Bm, float* __restrict__ C,
    int M, int Nn, int K, const float* __restrict__ bias, const float* __restrict__ res)
{
    tgemm_body<EPI, TB>(A, Bm, C, M, Nn, K, bias, res, blockIdx.y * 128, blockIdx.x * 128);
}

// fused Q,K,V projection: blockIdx.z selects weight/output
__global__ void __launch_bounds__(256, 2) tgemm_qkv(
    const float* __restrict__ A,
    const float* __restrict__ Wq, const float* __restrict__ Wk, const float* __restrict__ Wv,
    float* __restrict__ Cq, float* __restrict__ Ck, float* __restrict__ Cv)
{
    const float* Bm = (blockIdx.z == 0) ? Wq : (blockIdx.z == 1) ? Wk : Wv;
    float* C        = (blockIdx.z == 0) ? Cq : (blockIdx.z == 1) ? Ck : Cv;
    tgemm_body<EPI_NONE, false>(A, Bm, C, SB, ND, D_, nullptr, nullptr,
                                blockIdx.y * 128, blockIdx.x * 128);
}

// ---------------- ef[i,b,n,s] = (q + r_s_bias) . seg_embed[s] ----------------
__global__ void ef_kernel(const float* __restrict__ q, const float* __restrict__ rs,
                          const float* __restrict__ se, float* __restrict__ ef)
{
    int w = blockIdx.x * 4 + (threadIdx.x >> 5);   // over SB*NH
    int lane = threadIdx.x & 31;
    int row = w / NH, n = w % NH;
    int d0 = lane * 2;
    const float* qp = q + (size_t)row * ND + n * DH;
    float q0 = qp[d0]     + rs[n * DH + d0];
    float q1 = qp[d0 + 1] + rs[n * DH + d0 + 1];
    float s0 = q0 * se[(0 * NH + n) * DH + d0] + q1 * se[(0 * NH + n) * DH + d0 + 1];
    float s1 = q0 * se[(1 * NH + n) * DH + d0] + q1 * se[(1 * NH + n) * DH + d0 + 1];
    #pragma unroll
    for (int off = 16; off; off >>= 1) {
        s0 += __shfl_xor_sync(0xffffffffu, s0, off);
        s1 += __shfl_xor_sync(0xffffffffu, s1, off);
    }
    if (lane == 0) { ef[w * 2] = s0; ef[w * 2 + 1] = s1; }
}

// ---------------- fused relative-attention score ----------------
__global__ void __launch_bounds__(256) score_kernel(
    const float* __restrict__ q, const float* __restrict__ k, const float* __restrict__ kr,
    const float* __restrict__ rw, const float* __restrict__ rr,
    const float* __restrict__ ef, const float* __restrict__ seg_mat,
    const float* __restrict__ attn_mask, float* __restrict__ score)
{
    const int head = blockIdx.z;
    const int b = head / NH, n = head % NH;
    const int i0 = blockIdx.y * 64, j0 = blockIdx.x * 64;
    if (j0 > i0) return;   // fully-masked tile: never read downstream
    float* sc = score + (size_t)head * S_ * S_;
    const int tid = threadIdx.x;

    __shared__ float Qw[16][65], Qr[16][65], Kh[16][65], Krs[16][129];
    const int dl = tid & 15;
    const int lr = tid >> 4;
    const int r_base = S_ + j0 - i0 - 63;   // in [1, 961]
    const int tx = tid & 15, ty = tid >> 4;
    const int li0 = ty * 4, lj0 = tx * 4;

    float acc_ac[4][4], acc_bd[4][4];
    #pragma unroll
    for (int i = 0; i < 4; i++)
        #pragma unroll
        for (int j = 0; j < 4; j++) { acc_ac[i][j] = 0.f; acc_bd[i][j] = 0.f; }

    for (int kc = 0; kc < 4; kc++) {
        const int d0 = kc * 16;
        const float bw = rw[n * DH + d0 + dl];
        const float br = rr[n * DH + d0 + dl];
        #pragma unroll
        for (int s = 0; s < 4; s++) {
            int li = lr + s * 16;
            float qv = q[((size_t)((i0 + li) * B_ + b)) * ND + n * DH + d0 + dl];
            Qw[dl][li] = qv + bw;
            Qr[dl][li] = qv + br;
            Kh[dl][li] = k[((size_t)((j0 + li) * B_ + b)) * ND + n * DH + d0 + dl];
        }
        #pragma unroll
        for (int s = 0; s < 8; s++) {
            int lrr = lr + s * 16;
            Krs[dl][lrr] = kr[((size_t)((r_base + lrr) * B_ + b)) * ND + n * DH + d0 + dl];
        }
        __syncthreads();
        #pragma unroll
        for (int kk = 0; kk < 16; kk++) {
            float a[4], ar[4], bb[4];
            #pragma unroll
            for (int t = 0; t < 4; t++) {
                a[t]  = Qw[kk][li0 + t];
                ar[t] = Qr[kk][li0 + t];
                bb[t] = Kh[kk][lj0 + t];
            }
            #pragma unroll
            for (int i = 0; i < 4; i++)
                #pragma unroll
                for (int j = 0; j < 4; j++) {
                    acc_ac[i][j] += a[i] * bb[j];
                    acc_bd[i][j] += ar[i] * Krs[kk][lj0 + j - li0 - i + 63];
                }
        }
        __syncthreads();
    }

    const float scale = 0.125f;  // 1/sqrt(64)
    #pragma unroll
    for (int i = 0; i < 4; i++) {
        int gi = i0 + li0 + i;
        float ef0 = ef[((size_t)(gi * B_ + b) * NH + n) * 2 + 0];
        float ef1 = ef[((size_t)(gi * B_ + b) * NH + n) * 2 + 1];
        #pragma unroll
        for (int j = 0; j < 4; j++) {
            int gj = j0 + lj0 + j;
            const float* sm = seg_mat + (((size_t)gi * S_ + gj) * B_ + b) * 2;
            float msk = attn_mask[(size_t)gi * S_ + gj];
            float v = (acc_ac[i][j] + acc_bd[i][j] + sm[0] * ef0 + sm[1] * ef1) * scale
                      - 1e30f * msk;
            sc[(size_t)gi * S_ + gj] = v;
        }
    }
}

// ---------------- row softmax over valid causal prefix ----------------
__global__ void softmax_kernel(float* __restrict__ score)
{
    const int head = blockIdx.y, i = blockIdx.x;
    float* row = score + (size_t)head * S_ * S_ + (size_t)i * S_;
    const int L = ((i >> 6) + 1) << 6;   // padded to 64-tile; entries j>i are -1e30
    __shared__ float red[256];
    const int tid = threadIdx.x;
    float v[4];
    float mx = -3.0e38f;
    #pragma unroll
    for (int t = 0; t < 4; t++) {
        int idx = tid + t * 256;
        v[t] = (idx < L) ? row[idx] : -3.0e38f;
        mx = fmaxf(mx, v[t]);
    }
    red[tid] = mx; __syncthreads();
    for (int o = 128; o > 0; o >>= 1) { if (tid < o) red[tid] = fmaxf(red[tid], red[tid + o]); __syncthreads(); }
    mx = red[0]; __syncthreads();
    float s = 0.f;
    #pragma unroll
    for (int t = 0; t < 4; t++) { v[t] = expf(v[t] - mx); s += v[t]; }
    red[tid] = s; __syncthreads();
    for (int o = 128; o > 0; o >>= 1) { if (tid < o) red[tid] += red[tid + o]; __syncthreads(); }
    float inv = 1.0f / red[0];
    #pragma unroll
    for (int t = 0; t < 4; t++) {
        int idx = tid + t * 256;
        if (idx < L) row[idx] = v[t] * inv;
    }
}

// ---------------- vec = prob @ V per head (causal K truncation) ----------------
__global__ void __launch_bounds__(256) av_kernel(
    const float* __restrict__ prob, const float* __restrict__ v, float* __restrict__ vec)
{
    const int head = blockIdx.y;
    const int b = head / NH, n = head % NH;
    const int i0 = blockIdx.x * 64;
    const float* pr = prob + (size_t)head * S_ * S_;
    __shared__ float Ps[16][65];
    __shared__ float Vs[16][64];
    const int tid = threadIdx.x;
    const int tx = tid & 15, ty = tid >> 4;
    const int dl = tid & 15, lq = tid >> 4;
    const int vc = tid & 63, vr = tid >> 6;     // vr 0..3
    float acc[4][4];
    #pragma unroll
    for (int i = 0; i < 4; i++)
        #pragma unroll
        for (int j = 0; j < 4; j++) acc[i][j] = 0.f;

    const int kend = i0 + 64;  // prob[i, j>i] == 0
    for (int j0 = 0; j0 < kend; j0 += 16) {
        #pragma unroll
        for (int s = 0; s < 4; s++) {
            int li = lq + s * 16;
            Ps[dl][li] = pr[(size_t)(i0 + li) * S_ + j0 + dl];
        }
        #pragma unroll
        for (int s = 0; s < 4; s++) {
            int jr = vr + s * 4;
            Vs[jr][vc] = v[((size_t)((j0 + jr) * B_ + b)) * ND + n * DH + vc];
        }
        __syncthreads();
        #pragma unroll
        for (int kk = 0; kk < 16; kk++) {
            float p[4], vv[4];
            #pragma unroll
            for (int t = 0; t < 4; t++) p[t] = Ps[kk][ty * 4 + t];
            *(float4*)vv = *(const float4*)&Vs[kk][tx * 4];
            #pragma unroll
            for (int i = 0; i < 4; i++)
                #pragma unroll
                for (int j = 0; j < 4; j++)
                    acc[i][j] += p[i] * vv[j];
        }
        __syncthreads();
    }
    #pragma unroll
    for (int i = 0; i < 4; i++) {
        int gi = i0 + ty * 4 + i;
        #pragma unroll
        for (int j = 0; j < 4; j++)
            vec[((size_t)(gi * B_ + b)) * ND + n * DH + tx * 4 + j] = acc[i][j];
    }
}

// ---------------- layernorm (optional fused residual add) ----------------
__global__ void ln_kernel(const float* __restrict__ x, const float* __restrict__ res,
                          const float* __restrict__ g, const float* __restrict__ b,
                          float* __restrict__ out)
{
    __shared__ float red[256];
    const int row = blockIdx.x, tid = threadIdx.x;
    const float* xr = x + (size_t)row * D_;
    float v[4];
    float s = 0.f;
    #pragma unroll
    for (int t = 0; t < 4; t++) {
        int d = tid + t * 256;
        v[t] = xr[d];
        if (res) v[t] += res[(size_t)row * D_ + d];
        s += v[t];
    }
    red[tid] = s; __syncthreads();
    for (int o = 128; o > 0; o >>= 1) { if (tid < o) red[tid] += red[tid + o]; __syncthreads(); }
    float mean = red[0] * (1.f / D_);
    __syncthreads();
    s = 0.f;
    #pragma unroll
    for (int t = 0; t < 4; t++) { float d2 = v[t] - mean; s += d2 * d2; }
    red[tid] = s; __syncthreads();
    for (int o = 128; o > 0; o >>= 1) { if (tid < o) red[tid] += red[tid + o]; __syncthreads(); }
    float inv = rsqrtf(red[0] * (1.f / D_) + 1e-12f);
    #pragma unroll
    for (int t = 0; t < 4; t++) {
        int d = tid + t * 256;
        out[(size_t)row * D_ + d] = (v[t] - mean) * inv * g[d] + b[d];
    }
}

// ---------------- host ----------------
static float* sym_addr(const void* sym) {
    void* p = nullptr;
    cudaGetSymbolAddress(&p, sym);
    return (float*)p;
}

extern "C" void kernel_launch(void* const* d_in, const int* in_sizes, int n_in,
                              void* d_out, int out_size)
{
    (void)in_sizes; (void)n_in; (void)out_size;
    const float* h         = (const float*)d_in[0];
    const float* pos_emb   = (const float*)d_in[1];
    const float* attn_mask = (const float*)d_in[2];
    const float* seg_mat   = (const float*)d_in[3];
    const float* Wq        = (const float*)d_in[4];
    const float* Wk        = (const float*)d_in[5];
    const float* Wv        = (const float*)d_in[6];
    const float* Wo        = (const float*)d_in[7];
    const float* Wr        = (const float*)d_in[8];
    const float* rw        = (const float*)d_in[9];
    const float* rr        = (const float*)d_in[10];
    const float* rs        = (const float*)d_in[11];
    const float* se        = (const float*)d_in[12];
    const float* ln1g      = (const float*)d_in[13];
    const float* ln1b      = (const float*)d_in[14];
    const float* w1        = (const float*)d_in[15];
    const float* b1        = (const float*)d_in[16];
    const float* w2        = (const float*)d_in[17];
    const float* b2        = (const float*)d_in[18];
    const float* ln2g      = (const float*)d_in[19];
    const float* ln2b      = (const float*)d_in[20];
    float* out = (float*)d_out;

    float* gq    = sym_addr(g_q);
    float* gk    = sym_addr(g_k);
    float* gv    = sym_addr(g_v);
    float* gkr   = sym_addr(g_kr);
    float* gef   = sym_addr(g_ef);
    float* gsc   = sym_addr(g_score);
    float* gvec  = sym_addr(g_vec);
    float* gattn = sym_addr(g_attn);
    float* gx    = sym_addr(g_x);
    float* gf    = sym_addr(g_f);
    float* gf2   = sym_addr(g_f2);
    float* gbuf  = sym_addr(g_buf);

    for (int l = 0; l < 2; l++) {
        const float* cur = (l == 0) ? h : gbuf;
        float* nxt = (l == 0) ? gbuf : out;
        const size_t woff = (size_t)l * D_ * ND;

        tgemm_qkv<<<dim3(ND / 128, SB / 128, 3), 256>>>(
            cur, Wq + woff, Wk + woff, Wv + woff, gq, gk, gv);
        tgemm<EPI_NONE, false><<<dim3(ND / 128, RB / 128), 256>>>(
            pos_emb, Wr + woff, gkr, RB, ND, D_, nullptr, nullptr);

        ef_kernel<<<SB * NH / 4, 128>>>(gq, rs + l * NH * DH, se + l * 2 * NH * DH, gef);

        score_kernel<<<dim3(S_ / 64, S_ / 64, NHEADS), 256>>>(
            gq, gk, gkr, rw + l * NH * DH, rr + l * NH * DH,
            gef, seg_mat, attn_mask, gsc);

        softmax_kernel<<<dim3(S_, NHEADS), 256>>>(gsc);

        av_kernel<<<dim3(S_ / 64, NHEADS), 256>>>(gsc, gv, gvec);

        tgemm<EPI_RES, true><<<dim3(D_ / 128, SB / 128), 256>>>(
            gvec, Wo + woff, gattn, SB, D_, ND, nullptr, cur);

        ln_kernel<<<SB, 256>>>(gattn, nullptr, ln1g + l * D_, ln1b + l * D_, gx);

        tgemm<EPI_BIAS_GELU, false><<<dim3(DI_ / 128, SB / 128), 256>>>(
            gx, w1 + (size_t)l * D_ * DI_, gf, SB, DI_, D_, b1 + l * DI_, nullptr);

        tgemm<EPI_BIAS, false><<<dim3(D_ / 128, SB / 128), 256>>>(
            gf, w2 + (size_t)l * DI_ * D_, gf2, SB, D_, DI_, b2 + l * D_, nullptr);

        ln_kernel<<<SB, 256>>>(gf2, gx, ln2g + l * D_, ln2b + l * D_, nxt);
    }
}

// round 5
// speedup vs baseline: 2.4181x; 1.2614x over previous
#include <cuda_runtime.h>
#include <math.h>

#define S_   1024
#define B_   2
#define D_   1024
#define NH   16
#define DH   64
#define DI_  4096
#define R_   2048
#define SB   (S_*B_)          // 2048
#define RB   (R_*B_)          // 4096
#define ND   (NH*DH)          // 1024
#define NHEADS (B_*NH)        // 32

// ---------------- scratch (device globals; no allocation allowed) ----------------
__device__ float g_q   [SB*ND];
__device__ float g_k   [SB*ND];
__device__ float g_v   [SB*ND];
__device__ float g_kr  [RB*ND];
__device__ float g_ef  [SB*NH*2];
__device__ float g_score[(size_t)NHEADS*S_*S_];   // 128 MiB
__device__ float g_vec [SB*ND];
__device__ float g_attn[SB*ND];
__device__ float g_x   [SB*ND];
__device__ float g_f   [SB*DI_];
__device__ float g_f2  [SB*ND];
__device__ float g_buf [SB*ND];

enum { EPI_NONE = 0, EPI_BIAS = 1, EPI_BIAS_GELU = 2, EPI_RES = 3 };

__device__ __forceinline__ float gelu_f(float x) {
    return 0.5f * x * (1.0f + erff(x * 0.7071067811865476f));
}

// ---------------- bf16 split helpers ----------------
__device__ __forceinline__ void split2(float x0, float x1, unsigned& hi, unsigned& lo) {
    unsigned h;
    asm("cvt.rn.bf16x2.f32 %0, %1, %2;" : "=r"(h) : "f"(x1), "f"(x0));
    float h0 = __uint_as_float(h << 16);
    float h1 = __uint_as_float(h & 0xffff0000u);
    float r0 = x0 - h0;
    float r1 = x1 - h1;
    unsigned l;
    asm("cvt.rn.bf16x2.f32 %0, %1, %2;" : "=r"(l) : "f"(r1), "f"(r0));
    hi = h; lo = l;
}

__device__ __forceinline__ void mma_bf16(float* c,
    unsigned a0, unsigned a1, unsigned a2, unsigned a3, unsigned b0, unsigned b1) {
    asm volatile(
        "mma.sync.aligned.m16n8k16.row.col.f32.bf16.bf16.f32 "
        "{%0,%1,%2,%3}, {%4,%5,%6,%7}, {%8,%9}, {%0,%1,%2,%3};\n"
        : "+f"(c[0]), "+f"(c[1]), "+f"(c[2]), "+f"(c[3])
        : "r"(a0), "r"(a1), "r"(a2), "r"(a3), "r"(b0), "r"(b1));
}

// ---------------- tensor-core 128x128 GEMM body, bf16 split, NN / NT ----------------
template<int EPI, bool TB>
__device__ __forceinline__ void tgemm_body(
    const float* __restrict__ A, const float* __restrict__ Bm, float* __restrict__ C,
    int M, int Nn, int K, const float* __restrict__ bias, const float* __restrict__ res,
    int m0, int n0)
{
    __shared__ unsigned Ah[2][8][136], Al[2][8][136];
    __shared__ unsigned Bh[2][8][136], Bl[2][8][136];
    const int tid = threadIdx.x;
    const int wid = tid >> 5, lane = tid & 31;
    const int wm = (wid >> 2) * 64;
    const int wn = (wid & 3) * 32;
    const int g  = lane >> 2;
    const int tg = lane & 3;

    const int lm = tid >> 1, lq = (tid & 1) * 8;
    const int bk = tid >> 5, bn = (tid & 31) * 4;

    float acc[4][4][4];
    #pragma unroll
    for (int mt = 0; mt < 4; mt++)
        #pragma unroll
        for (int nt = 0; nt < 4; nt++)
            #pragma unroll
            for (int r = 0; r < 4; r++) acc[mt][nt][r] = 0.f;

    float a_st[8], b_st[8];

    auto load_slab = [&](int k0) {
        *(float4*)(a_st)     = *(const float4*)(A + (size_t)(m0 + lm) * K + k0 + lq);
        *(float4*)(a_st + 4) = *(const float4*)(A + (size_t)(m0 + lm) * K + k0 + lq + 4);
        if (TB) {
            *(float4*)(b_st)     = *(const float4*)(Bm + (size_t)(n0 + lm) * K + k0 + lq);
            *(float4*)(b_st + 4) = *(const float4*)(Bm + (size_t)(n0 + lm) * K + k0 + lq + 4);
        } else {
            *(float4*)(b_st)     = *(const float4*)(Bm + (size_t)(k0 + 2 * bk) * Nn + n0 + bn);
            *(float4*)(b_st + 4) = *(const float4*)(Bm + (size_t)(k0 + 2 * bk + 1) * Nn + n0 + bn);
        }
    };

    auto store_slab = [&](int s) {
        #pragma unroll
        for (int j = 0; j < 4; j++) {
            unsigned hi, lo;
            split2(a_st[2 * j], a_st[2 * j + 1], hi, lo);
            Ah[s][(lq >> 1) + j][lm] = hi;
            Al[s][(lq >> 1) + j][lm] = lo;
        }
        if (TB) {
            #pragma unroll
            for (int j = 0; j < 4; j++) {
                unsigned hi, lo;
                split2(b_st[2 * j], b_st[2 * j + 1], hi, lo);
                Bh[s][(lq >> 1) + j][lm] = hi;
                Bl[s][(lq >> 1) + j][lm] = lo;
            }
        } else {
            #pragma unroll
            for (int j = 0; j < 4; j++) {
                unsigned hi, lo;
                split2(b_st[j], b_st[4 + j], hi, lo);
                Bh[s][bk][bn + j] = hi;
                Bl[s][bk][bn + j] = lo;
            }
        }
    };

    auto compute = [&](int s) {
        unsigned bh0[4], bh1[4], bl0[4], bl1[4];
        #pragma unroll
        for (int nt = 0; nt < 4; nt++) {
            int c = wn + nt * 8 + g;
            bh0[nt] = Bh[s][tg][c];     bh1[nt] = Bh[s][tg + 4][c];
            bl0[nt] = Bl[s][tg][c];     bl1[nt] = Bl[s][tg + 4][c];
        }
        #pragma unroll
        for (int mt = 0; mt < 4; mt++) {
            int r0c = wm + mt * 16 + g;
            unsigned ah0 = Ah[s][tg][r0c],     ah1 = Ah[s][tg][r0c + 8];
            unsigned ah2 = Ah[s][tg + 4][r0c], ah3 = Ah[s][tg + 4][r0c + 8];
            unsigned al0 = Al[s][tg][r0c],     al1 = Al[s][tg][r0c + 8];
            unsigned al2 = Al[s][tg + 4][r0c], al3 = Al[s][tg + 4][r0c + 8];
            #pragma unroll
            for (int nt = 0; nt < 4; nt++) {
                float* c = acc[mt][nt];
                mma_bf16(c, ah0, ah1, ah2, ah3, bh0[nt], bh1[nt]);
                mma_bf16(c, ah0, ah1, ah2, ah3, bl0[nt], bl1[nt]);
                mma_bf16(c, al0, al1, al2, al3, bh0[nt], bh1[nt]);
            }
        }
    };

    const int nslab = K >> 4;
    load_slab(0);
    store_slab(0);
    __syncthreads();
    for (int kt = 0; kt < nslab; kt++) {
        if (kt + 1 < nslab) load_slab((kt + 1) << 4);
        compute(kt & 1);
        if (kt + 1 < nslab) store_slab((kt + 1) & 1);
        __syncthreads();
    }

    #pragma unroll
    for (int mt = 0; mt < 4; mt++) {
        int r0 = m0 + wm + mt * 16 + g;
        #pragma unroll
        for (int nt = 0; nt < 4; nt++) {
            int c0 = n0 + wn + nt * 8 + tg * 2;
            #pragma unroll
            for (int r = 0; r < 4; r++) {
                int mm = r0 + (r >> 1) * 8;
                int nn = c0 + (r & 1);
                float v = acc[mt][nt][r];
                if (EPI == EPI_BIAS || EPI == EPI_BIAS_GELU) v += bias[nn];
                if (EPI == EPI_BIAS_GELU) v = gelu_f(v);
                if (EPI == EPI_RES) v += res[(size_t)mm * Nn + nn];
                C[(size_t)mm * Nn + nn] = v;
            }
        }
    }
}

template<int EPI, bool TB>
__global__ void __launch_bounds__(256, 2) tgemm(
    const float* __restrict__ A, const float* __restrict__ Bm, float* __restrict__ C,
    int M, int Nn, int K, const float* __restrict__ bias, const float* __restrict__ res)
{
    tgemm_body<EPI, TB>(A, Bm, C, M, Nn, K, bias, res, blockIdx.y * 128, blockIdx.x * 128);
}

// fused Q,K,V projection: blockIdx.z selects weight/output
__global__ void __launch_bounds__(256, 2) tgemm_qkv(
    const float* __restrict__ A,
    const float* __restrict__ Wq, const float* __restrict__ Wk, const float* __restrict__ Wv,
    float* __restrict__ Cq, float* __restrict__ Ck, float* __restrict__ Cv)
{
    const float* Bm = (blockIdx.z == 0) ? Wq : (blockIdx.z == 1) ? Wk : Wv;
    float* C        = (blockIdx.z == 0) ? Cq : (blockIdx.z == 1) ? Ck : Cv;
    tgemm_body<EPI_NONE, false>(A, Bm, C, SB, ND, D_, nullptr, nullptr,
                                blockIdx.y * 128, blockIdx.x * 128);
}

// ---------------- ef[i,b,n,s] = (q + r_s_bias) . seg_embed[s] ----------------
__global__ void ef_kernel(const float* __restrict__ q, const float* __restrict__ rs,
                          const float* __restrict__ se, float* __restrict__ ef)
{
    int w = blockIdx.x * 4 + (threadIdx.x >> 5);   // over SB*NH
    int lane = threadIdx.x & 31;
    int row = w / NH, n = w % NH;
    int d0 = lane * 2;
    const float* qp = q + (size_t)row * ND + n * DH;
    float q0 = qp[d0]     + rs[n * DH + d0];
    float q1 = qp[d0 + 1] + rs[n * DH + d0 + 1];
    float s0 = q0 * se[(0 * NH + n) * DH + d0] + q1 * se[(0 * NH + n) * DH + d0 + 1];
    float s1 = q0 * se[(1 * NH + n) * DH + d0] + q1 * se[(1 * NH + n) * DH + d0 + 1];
    #pragma unroll
    for (int off = 16; off; off >>= 1) {
        s0 += __shfl_xor_sync(0xffffffffu, s0, off);
        s1 += __shfl_xor_sync(0xffffffffu, s1, off);
    }
    if (lane == 0) { ef[w * 2] = s0; ef[w * 2 + 1] = s1; }
}

// ---------------- tensor-core relative-attention score ----------------
// Per 64x64 causal tile:
//   ac  (64x64)  = (q+rw) . K^T          (warps 0-3)
//   Dloc(64x128) = (q+rr) . Krs_window^T (warps 4-11)
//   score[i,j] = (ac + Dloc[li, lj-li+63] + ef_seg) * scale,  -1e30 if j>i
__global__ void __launch_bounds__(384, 2) score_mma(
    const float* __restrict__ q, const float* __restrict__ k, const float* __restrict__ kr,
    const float* __restrict__ rw, const float* __restrict__ rr,
    const float* __restrict__ ef, const float* __restrict__ seg_mat,
    float* __restrict__ score)
{
    const int head = blockIdx.z;
    const int b = head / NH, n = head % NH;
    const int i0 = blockIdx.y * 64, j0 = blockIdx.x * 64;
    if (j0 > i0) return;
    float* sc = score + (size_t)head * S_ * S_;

    __shared__ union {
        struct {
            unsigned QA[4][16][72];    // [Qw_hi,Qw_lo,Qr_hi,Qr_lo][kpair][row]
            unsigned Bm[2][16][200];   // [hi,lo][kpair][col: 0..63=K, 64..191=Krs]
        } s;
        float dloc[64][132];
    } u;
    __shared__ float ef_s[64][2];

    const int tid = threadIdx.x;
    const int wid = tid >> 5, lane = tid & 31;
    const int g = lane >> 2, tg = lane & 3;
    const int r_base = S_ + j0 - i0 - 63;   // in [1, 961]

    float acc[8][4];
    #pragma unroll
    for (int f = 0; f < 8; f++)
        #pragma unroll
        for (int r = 0; r < 4; r++) acc[f][r] = 0.f;

    const bool is_ac = (wid < 4);
    const int aw = is_ac ? wid : (wid - 4);
    const int r0 = (is_ac ? aw : (aw >> 1)) * 16;
    const int cbase = is_ac ? 0 : 64 + (aw & 1) * 64;
    const int aselh = is_ac ? 0 : 2;

    for (int ks = 0; ks < 2; ks++) {
        const int kbase = ks * 32;
        // --- load Qw/Qr (64 rows x 32 k) ---
        for (int job = tid; job < 512; job += 384) {
            int li = job >> 3, kq = (job & 7) * 4;
            int kk = kbase + kq;
            const float* qp = q + ((size_t)((i0 + li) * B_ + b)) * ND + n * DH + kk;
            float4 qv = *(const float4*)qp;
            float4 wv = *(const float4*)(rw + n * DH + kk);
            float4 rv = *(const float4*)(rr + n * DH + kk);
            unsigned hi, lo;
            int kp = kq >> 1;
            split2(qv.x + wv.x, qv.y + wv.y, hi, lo);
            u.s.QA[0][kp][li] = hi; u.s.QA[1][kp][li] = lo;
            split2(qv.z + wv.z, qv.w + wv.w, hi, lo);
            u.s.QA[0][kp + 1][li] = hi; u.s.QA[1][kp + 1][li] = lo;
            split2(qv.x + rv.x, qv.y + rv.y, hi, lo);
            u.s.QA[2][kp][li] = hi; u.s.QA[3][kp][li] = lo;
            split2(qv.z + rv.z, qv.w + rv.w, hi, lo);
            u.s.QA[2][kp + 1][li] = hi; u.s.QA[3][kp + 1][li] = lo;
        }
        // --- load K (64 rows) ---
        for (int job = tid; job < 512; job += 384) {
            int li = job >> 3, kq = (job & 7) * 4;
            float4 kv = *(const float4*)(k + ((size_t)((j0 + li) * B_ + b)) * ND + n * DH + kbase + kq);
            unsigned hi, lo;
            int kp = kq >> 1;
            split2(kv.x, kv.y, hi, lo);
            u.s.Bm[0][kp][li] = hi; u.s.Bm[1][kp][li] = lo;
            split2(kv.z, kv.w, hi, lo);
            u.s.Bm[0][kp + 1][li] = hi; u.s.Bm[1][kp + 1][li] = lo;
        }
        // --- load Krs window (128 rows) ---
        for (int job = tid; job < 1024; job += 384) {
            int lr = job >> 3, kq = (job & 7) * 4;
            float4 kv = *(const float4*)(kr + ((size_t)((r_base + lr) * B_ + b)) * ND + n * DH + kbase + kq);
            unsigned hi, lo;
            int kp = kq >> 1, col = 64 + lr;
            split2(kv.x, kv.y, hi, lo);
            u.s.Bm[0][kp][col] = hi; u.s.Bm[1][kp][col] = lo;
            split2(kv.z, kv.w, hi, lo);
            u.s.Bm[0][kp + 1][col] = hi; u.s.Bm[1][kp + 1][col] = lo;
        }
        if (ks == 0) {
            for (int e = tid; e < 128; e += 384)
                ef_s[e >> 1][e & 1] =
                    ef[((size_t)((i0 + (e >> 1)) * B_ + b) * NH + n) * 2 + (e & 1)];
        }
        __syncthreads();

        #pragma unroll
        for (int kf = 0; kf < 2; kf++) {
            int kp = kf * 8;
            unsigned ah0 = u.s.QA[aselh][kp + tg][r0 + g];
            unsigned ah1 = u.s.QA[aselh][kp + tg][r0 + g + 8];
            unsigned ah2 = u.s.QA[aselh][kp + tg + 4][r0 + g];
            unsigned ah3 = u.s.QA[aselh][kp + tg + 4][r0 + g + 8];
            unsigned al0 = u.s.QA[aselh + 1][kp + tg][r0 + g];
            unsigned al1 = u.s.QA[aselh + 1][kp + tg][r0 + g + 8];
            unsigned al2 = u.s.QA[aselh + 1][kp + tg + 4][r0 + g];
            unsigned al3 = u.s.QA[aselh + 1][kp + tg + 4][r0 + g + 8];
            #pragma unroll
            for (int f = 0; f < 8; f++) {
                int c = cbase + f * 8 + g;
                unsigned bh0 = u.s.Bm[0][kp + tg][c], bh1 = u.s.Bm[0][kp + tg + 4][c];
                unsigned bl0 = u.s.Bm[1][kp + tg][c], bl1 = u.s.Bm[1][kp + tg + 4][c];
                mma_bf16(acc[f], ah0, ah1, ah2, ah3, bh0, bh1);
                mma_bf16(acc[f], ah0, ah1, ah2, ah3, bl0, bl1);
                mma_bf16(acc[f], al0, al1, al2, al3, bh0, bh1);
            }
        }
        __syncthreads();
    }

    // warps 4-11: dump Dloc to smem (overlays operand buffers)
    if (!is_ac) {
        int ub = (aw & 1) * 64;
        #pragma unroll
        for (int f = 0; f < 8; f++)
            #pragma unroll
            for (int r = 0; r < 4; r++)
                u.dloc[r0 + g + (r >> 1) * 8][ub + f * 8 + tg * 2 + (r & 1)] = acc[f][r];
    }
    __syncthreads();

    // warps 0-3: combine and store
    if (is_ac) {
        const float scale = 0.125f;
        #pragma unroll
        for (int f = 0; f < 8; f++) {
            #pragma unroll
            for (int r = 0; r < 4; r++) {
                int li = r0 + g + (r >> 1) * 8;
                int lj = f * 8 + tg * 2 + (r & 1);
                int gi = i0 + li, gj = j0 + lj;
                float v;
                if (gj > gi) {
                    v = -1e30f;
                } else {
                    float dl = u.dloc[li][lj - li + 63];
                    float diff = seg_mat[(((size_t)gi * S_ + gj) * B_ + b) * 2 + 1];
                    float e0 = ef_s[li][0], e1 = ef_s[li][1];
                    v = (acc[f][r] + dl + e0 + diff * (e1 - e0)) * scale;
                }
                sc[(size_t)gi * S_ + gj] = v;
            }
        }
    }
}

// ---------------- row softmax over valid causal prefix ----------------
__global__ void softmax_kernel(float* __restrict__ score)
{
    const int head = blockIdx.y, i = blockIdx.x;
    float* row = score + (size_t)head * S_ * S_ + (size_t)i * S_;
    const int L = ((i >> 6) + 1) << 6;   // padded to 64-tile; entries j>i are -1e30
    __shared__ float red[256];
    const int tid = threadIdx.x;
    float v[4];
    float mx = -3.0e38f;
    #pragma unroll
    for (int t = 0; t < 4; t++) {
        int idx = tid + t * 256;
        v[t] = (idx < L) ? row[idx] : -3.0e38f;
        mx = fmaxf(mx, v[t]);
    }
    red[tid] = mx; __syncthreads();
    for (int o = 128; o > 0; o >>= 1) { if (tid < o) red[tid] = fmaxf(red[tid], red[tid + o]); __syncthreads(); }
    mx = red[0]; __syncthreads();
    float s = 0.f;
    #pragma unroll
    for (int t = 0; t < 4; t++) { v[t] = expf(v[t] - mx); s += v[t]; }
    red[tid] = s; __syncthreads();
    for (int o = 128; o > 0; o >>= 1) { if (tid < o) red[tid] += red[tid + o]; __syncthreads(); }
    float inv = 1.0f / red[0];
    #pragma unroll
    for (int t = 0; t < 4; t++) {
        int idx = tid + t * 256;
        if (idx < L) row[idx] = v[t] * inv;
    }
}

// ---------------- vec = prob @ V via bf16-split MMA (causal K truncation) ----------------
__global__ void __launch_bounds__(256, 3) av_mma(
    const float* __restrict__ prob, const float* __restrict__ v, float* __restrict__ vec)
{
    const int head = blockIdx.y;
    const int b = head / NH, n = head % NH;
    const int i0 = blockIdx.x * 64;
    const float* pr = prob + (size_t)head * S_ * S_;
    __shared__ unsigned Ph[16][72], Pl[16][72], Vh[16][72], Vl[16][72];
    const int tid = threadIdx.x;
    const int wid = tid >> 5, lane = tid & 31;
    const int g = lane >> 2, tg = lane & 3;
    const int r0 = (wid >> 1) * 16, dbase = (wid & 1) * 32;

    float acc[4][4];
    #pragma unroll
    for (int f = 0; f < 4; f++)
        #pragma unroll
        for (int r = 0; r < 4; r++) acc[f][r] = 0.f;

    const int kend = i0 + 64;
    for (int js = 0; js < kend; js += 32) {
        // prob rows i0..i0+63, k js..js+31
        #pragma unroll
        for (int t = 0; t < 2; t++) {
            int job = tid + t * 256;
            int li = job >> 3, kq = (job & 7) * 4;
            float4 pv = *(const float4*)(pr + (size_t)(i0 + li) * S_ + js + kq);
            unsigned hi, lo;
            int kp = kq >> 1;
            split2(pv.x, pv.y, hi, lo); Ph[kp][li] = hi; Pl[kp][li] = lo;
            split2(pv.z, pv.w, hi, lo); Ph[kp + 1][li] = hi; Pl[kp + 1][li] = lo;
        }
        // V transposed: kpair jp (rows js+2jp, js+2jp+1), d quad
        {
            int jp = tid >> 4, dq = (tid & 15) * 4;
            const float* vp0 = v + ((size_t)((js + 2 * jp) * B_ + b)) * ND + n * DH + dq;
            const float* vp1 = vp0 + (size_t)B_ * ND;
            float4 v0 = *(const float4*)vp0, v1 = *(const float4*)vp1;
            unsigned hi, lo;
            split2(v0.x, v1.x, hi, lo); Vh[jp][dq] = hi;     Vl[jp][dq] = lo;
            split2(v0.y, v1.y, hi, lo); Vh[jp][dq + 1] = hi; Vl[jp][dq + 1] = lo;
            split2(v0.z, v1.z, hi, lo); Vh[jp][dq + 2] = hi; Vl[jp][dq + 2] = lo;
            split2(v0.w, v1.w, hi, lo); Vh[jp][dq + 3] = hi; Vl[jp][dq + 3] = lo;
        }
        __syncthreads();
        #pragma unroll
        for (int kf = 0; kf < 2; kf++) {
            int kp = kf * 8;
            unsigned ah0 = Ph[kp + tg][r0 + g],     ah1 = Ph[kp + tg][r0 + g + 8];
            unsigned ah2 = Ph[kp + tg + 4][r0 + g], ah3 = Ph[kp + tg + 4][r0 + g + 8];
            unsigned al0 = Pl[kp + tg][r0 + g],     al1 = Pl[kp + tg][r0 + g + 8];
            unsigned al2 = Pl[kp + tg + 4][r0 + g], al3 = Pl[kp + tg + 4][r0 + g + 8];
            #pragma unroll
            for (int f = 0; f < 4; f++) {
                int c = dbase + f * 8 + g;
                unsigned bh0 = Vh[kp + tg][c], bh1 = Vh[kp + tg + 4][c];
                unsigned bl0 = Vl[kp + tg][c], bl1 = Vl[kp + tg + 4][c];
                mma_bf16(acc[f], ah0, ah1, ah2, ah3, bh0, bh1);
                mma_bf16(acc[f], ah0, ah1, ah2, ah3, bl0, bl1);
                mma_bf16(acc[f], al0, al1, al2, al3, bh0, bh1);
            }
        }
        __syncthreads();
    }
    #pragma unroll
    for (int f = 0; f < 4; f++)
        #pragma unroll
        for (int r = 0; r < 4; r++) {
            int gi = i0 + r0 + g + (r >> 1) * 8;
            int d = dbase + f * 8 + tg * 2 + (r & 1);
            vec[((size_t)(gi * B_ + b)) * ND + n * DH + d] = acc[f][r];
        }
}

// ---------------- layernorm (optional fused residual add) ----------------
__global__ void ln_kernel(const float* __restrict__ x, const float* __restrict__ res,
                          const float* __restrict__ g, const float* __restrict__ b,
                          float* __restrict__ out)
{
    __shared__ float red[256];
    const int row = blockIdx.x, tid = threadIdx.x;
    const float* xr = x + (size_t)row * D_;
    float v[4];
    float s = 0.f;
    #pragma unroll
    for (int t = 0; t < 4; t++) {
        int d = tid + t * 256;
        v[t] = xr[d];
        if (res) v[t] += res[(size_t)row * D_ + d];
        s += v[t];
    }
    red[tid] = s; __syncthreads();
    for (int o = 128; o > 0; o >>= 1) { if (tid < o) red[tid] += red[tid + o]; __syncthreads(); }
    float mean = red[0] * (1.f / D_);
    __syncthreads();
    s = 0.f;
    #pragma unroll
    for (int t = 0; t < 4; t++) { float d2 = v[t] - mean; s += d2 * d2; }
    red[tid] = s; __syncthreads();
    for (int o = 128; o > 0; o >>= 1) { if (tid < o) red[tid] += red[tid + o]; __syncthreads(); }
    float inv = rsqrtf(red[0] * (1.f / D_) + 1e-12f);
    #pragma unroll
    for (int t = 0; t < 4; t++) {
        int d = tid + t * 256;
        out[(size_t)row * D_ + d] = (v[t] - mean) * inv * g[d] + b[d];
    }
}

// ---------------- host ----------------
static float* sym_addr(const void* sym) {
    void* p = nullptr;
    cudaGetSymbolAddress(&p, sym);
    return (float*)p;
}

extern "C" void kernel_launch(void* const* d_in, const int* in_sizes, int n_in,
                              void* d_out, int out_size)
{
    (void)in_sizes; (void)n_in; (void)out_size;
    const float* h         = (const float*)d_in[0];
    const float* pos_emb   = (const float*)d_in[1];
    const float* seg_mat   = (const float*)d_in[3];
    const float* Wq        = (const float*)d_in[4];
    const float* Wk        = (const float*)d_in[5];
    const float* Wv        = (const float*)d_in[6];
    const float* Wo        = (const float*)d_in[7];
    const float* Wr        = (const float*)d_in[8];
    const float* rw        = (const float*)d_in[9];
    const float* rr        = (const float*)d_in[10];
    const float* rs        = (const float*)d_in[11];
    const float* se        = (const float*)d_in[12];
    const float* ln1g      = (const float*)d_in[13];
    const float* ln1b      = (const float*)d_in[14];
    const float* w1        = (const float*)d_in[15];
    const float* b1        = (const float*)d_in[16];
    const float* w2        = (const float*)d_in[17];
    const float* b2        = (const float*)d_in[18];
    const float* ln2g      = (const float*)d_in[19];
    const float* ln2b      = (const float*)d_in[20];
    float* out = (float*)d_out;

    float* gq    = sym_addr(g_q);
    float* gk    = sym_addr(g_k);
    float* gv    = sym_addr(g_v);
    float* gkr   = sym_addr(g_kr);
    float* gef   = sym_addr(g_ef);
    float* gsc   = sym_addr(g_score);
    float* gvec  = sym_addr(g_vec);
    float* gattn = sym_addr(g_attn);
    float* gx    = sym_addr(g_x);
    float* gf    = sym_addr(g_f);
    float* gf2   = sym_addr(g_f2);
    float* gbuf  = sym_addr(g_buf);

    for (int l = 0; l < 2; l++) {
        const float* cur = (l == 0) ? h : gbuf;
        float* nxt = (l == 0) ? gbuf : out;
        const size_t woff = (size_t)l * D_ * ND;

        tgemm_qkv<<<dim3(ND / 128, SB / 128, 3), 256>>>(
            cur, Wq + woff, Wk + woff, Wv + woff, gq, gk, gv);
        tgemm<EPI_NONE, false><<<dim3(ND / 128, RB / 128), 256>>>(
            pos_emb, Wr + woff, gkr, RB, ND, D_, nullptr, nullptr);

        ef_kernel<<<SB * NH / 4, 128>>>(gq, rs + l * NH * DH, se + l * 2 * NH * DH, gef);

        score_mma<<<dim3(S_ / 64, S_ / 64, NHEADS), 384>>>(
            gq, gk, gkr, rw + l * NH * DH, rr + l * NH * DH,
            gef, seg_mat, gsc);

        softmax_kernel<<<dim3(S_, NHEADS), 256>>>(gsc);

        av_mma<<<dim3(S_ / 64, NHEADS), 256>>>(gsc, gv, gvec);

        tgemm<EPI_RES, true><<<dim3(D_ / 128, SB / 128), 256>>>(
            gvec, Wo + woff, gattn, SB, D_, ND, nullptr, cur);

        ln_kernel<<<SB, 256>>>(gattn, nullptr, ln1g + l * D_, ln1b + l * D_, gx);

        tgemm<EPI_BIAS_GELU, false><<<dim3(DI_ / 128, SB / 128), 256>>>(
            gx, w1 + (size_t)l * D_ * DI_, gf, SB, DI_, D_, b1 + l * DI_, nullptr);

        tgemm<EPI_BIAS, false><<<dim3(D_ / 128, SB / 128), 256>>>(
            gf, w2 + (size_t)l * DI_ * D_, gf2, SB, D_, DI_, b2 + l * D_, nullptr);

        ln_kernel<<<SB, 256>>>(gf2, gx, ln2g + l * D_, ln2b + l * D_, nxt);
    }
}

// round 6
// speedup vs baseline: 2.6386x; 1.0912x over previous
#include <cuda_runtime.h>
#include <math.h>

#define S_   1024
#define B_   2
#define D_   1024
#define NH   16
#define DH   64
#define DI_  4096
#define R_   2048
#define SB   (S_*B_)          // 2048
#define RB   (R_*B_)          // 4096
#define ND   (NH*DH)          // 1024
#define NHEADS (B_*NH)        // 32

// ---------------- scratch (device globals; no allocation allowed) ----------------
__device__ float g_q   [SB*ND];
__device__ float g_k   [SB*ND];
__device__ float g_v   [SB*ND];
__device__ float g_kr  [RB*ND];
__device__ float g_ef  [SB*NH*2];
__device__ float g_vec [SB*ND];
__device__ float g_attn[SB*ND];
__device__ float g_x   [SB*ND];
__device__ float g_f   [SB*DI_];
__device__ float g_f2  [SB*ND];
__device__ float g_buf [SB*ND];

enum { EPI_NONE = 0, EPI_BIAS = 1, EPI_BIAS_GELU = 2, EPI_RES = 3 };

__device__ __forceinline__ float gelu_f(float x) {
    return 0.5f * x * (1.0f + erff(x * 0.7071067811865476f));
}

// ---------------- bf16 split helpers ----------------
__device__ __forceinline__ void split2(float x0, float x1, unsigned& hi, unsigned& lo) {
    unsigned h;
    asm("cvt.rn.bf16x2.f32 %0, %1, %2;" : "=r"(h) : "f"(x1), "f"(x0));
    float h0 = __uint_as_float(h << 16);
    float h1 = __uint_as_float(h & 0xffff0000u);
    float r0 = x0 - h0;
    float r1 = x1 - h1;
    unsigned l;
    asm("cvt.rn.bf16x2.f32 %0, %1, %2;" : "=r"(l) : "f"(r1), "f"(r0));
    hi = h; lo = l;
}

__device__ __forceinline__ void mma_bf16(float* c,
    unsigned a0, unsigned a1, unsigned a2, unsigned a3, unsigned b0, unsigned b1) {
    asm volatile(
        "mma.sync.aligned.m16n8k16.row.col.f32.bf16.bf16.f32 "
        "{%0,%1,%2,%3}, {%4,%5,%6,%7}, {%8,%9}, {%0,%1,%2,%3};\n"
        : "+f"(c[0]), "+f"(c[1]), "+f"(c[2]), "+f"(c[3])
        : "r"(a0), "r"(a1), "r"(a2), "r"(a3), "r"(b0), "r"(b1));
}

// ---------------- tensor-core 128x128 GEMM body, bf16 split, NN / NT ----------------
template<int EPI, bool TB>
__device__ __forceinline__ void tgemm_body(
    const float* __restrict__ A, const float* __restrict__ Bm, float* __restrict__ C,
    int M, int Nn, int K, const float* __restrict__ bias, const float* __restrict__ res,
    int m0, int n0)
{
    __shared__ unsigned Ah[2][8][136], Al[2][8][136];
    __shared__ unsigned Bh[2][8][136], Bl[2][8][136];
    const int tid = threadIdx.x;
    const int wid = tid >> 5, lane = tid & 31;
    const int wm = (wid >> 2) * 64;
    const int wn = (wid & 3) * 32;
    const int g  = lane >> 2;
    const int tg = lane & 3;

    const int lm = tid >> 1, lq = (tid & 1) * 8;
    const int bk = tid >> 5, bn = (tid & 31) * 4;

    float acc[4][4][4];
    #pragma unroll
    for (int mt = 0; mt < 4; mt++)
        #pragma unroll
        for (int nt = 0; nt < 4; nt++)
            #pragma unroll
            for (int r = 0; r < 4; r++) acc[mt][nt][r] = 0.f;

    float a_st[8], b_st[8];

    auto load_slab = [&](int k0) {
        *(float4*)(a_st)     = *(const float4*)(A + (size_t)(m0 + lm) * K + k0 + lq);
        *(float4*)(a_st + 4) = *(const float4*)(A + (size_t)(m0 + lm) * K + k0 + lq + 4);
        if (TB) {
            *(float4*)(b_st)     = *(const float4*)(Bm + (size_t)(n0 + lm) * K + k0 + lq);
            *(float4*)(b_st + 4) = *(const float4*)(Bm + (size_t)(n0 + lm) * K + k0 + lq + 4);
        } else {
            *(float4*)(b_st)     = *(const float4*)(Bm + (size_t)(k0 + 2 * bk) * Nn + n0 + bn);
            *(float4*)(b_st + 4) = *(const float4*)(Bm + (size_t)(k0 + 2 * bk + 1) * Nn + n0 + bn);
        }
    };

    auto store_slab = [&](int s) {
        #pragma unroll
        for (int j = 0; j < 4; j++) {
            unsigned hi, lo;
            split2(a_st[2 * j], a_st[2 * j + 1], hi, lo);
            Ah[s][(lq >> 1) + j][lm] = hi;
            Al[s][(lq >> 1) + j][lm] = lo;
        }
        if (TB) {
            #pragma unroll
            for (int j = 0; j < 4; j++) {
                unsigned hi, lo;
                split2(b_st[2 * j], b_st[2 * j + 1], hi, lo);
                Bh[s][(lq >> 1) + j][lm] = hi;
                Bl[s][(lq >> 1) + j][lm] = lo;
            }
        } else {
            #pragma unroll
            for (int j = 0; j < 4; j++) {
                unsigned hi, lo;
                split2(b_st[j], b_st[4 + j], hi, lo);
                Bh[s][bk][bn + j] = hi;
                Bl[s][bk][bn + j] = lo;
            }
        }
    };

    auto compute = [&](int s) {
        unsigned bh0[4], bh1[4], bl0[4], bl1[4];
        #pragma unroll
        for (int nt = 0; nt < 4; nt++) {
            int c = wn + nt * 8 + g;
            bh0[nt] = Bh[s][tg][c];     bh1[nt] = Bh[s][tg + 4][c];
            bl0[nt] = Bl[s][tg][c];     bl1[nt] = Bl[s][tg + 4][c];
        }
        #pragma unroll
        for (int mt = 0; mt < 4; mt++) {
            int r0c = wm + mt * 16 + g;
            unsigned ah0 = Ah[s][tg][r0c],     ah1 = Ah[s][tg][r0c + 8];
            unsigned ah2 = Ah[s][tg + 4][r0c], ah3 = Ah[s][tg + 4][r0c + 8];
            unsigned al0 = Al[s][tg][r0c],     al1 = Al[s][tg][r0c + 8];
            unsigned al2 = Al[s][tg + 4][r0c], al3 = Al[s][tg + 4][r0c + 8];
            #pragma unroll
            for (int nt = 0; nt < 4; nt++) {
                float* c = acc[mt][nt];
                mma_bf16(c, ah0, ah1, ah2, ah3, bh0[nt], bh1[nt]);
                mma_bf16(c, ah0, ah1, ah2, ah3, bl0[nt], bl1[nt]);
                mma_bf16(c, al0, al1, al2, al3, bh0[nt], bh1[nt]);
            }
        }
    };

    const int nslab = K >> 4;
    load_slab(0);
    store_slab(0);
    __syncthreads();
    for (int kt = 0; kt < nslab; kt++) {
        if (kt + 1 < nslab) load_slab((kt + 1) << 4);
        compute(kt & 1);
        if (kt + 1 < nslab) store_slab((kt + 1) & 1);
        __syncthreads();
    }

    #pragma unroll
    for (int mt = 0; mt < 4; mt++) {
        int r0 = m0 + wm + mt * 16 + g;
        #pragma unroll
        for (int nt = 0; nt < 4; nt++) {
            int c0 = n0 + wn + nt * 8 + tg * 2;
            #pragma unroll
            for (int r = 0; r < 4; r++) {
                int mm = r0 + (r >> 1) * 8;
                int nn = c0 + (r & 1);
                float v = acc[mt][nt][r];
                if (EPI == EPI_BIAS || EPI == EPI_BIAS_GELU) v += bias[nn];
                if (EPI == EPI_BIAS_GELU) v = gelu_f(v);
                if (EPI == EPI_RES) v += res[(size_t)mm * Nn + nn];
                C[(size_t)mm * Nn + nn] = v;
            }
        }
    }
}

template<int EPI, bool TB>
__global__ void __launch_bounds__(256, 2) tgemm(
    const float* __restrict__ A, const float* __restrict__ Bm, float* __restrict__ C,
    int M, int Nn, int K, const float* __restrict__ bias, const float* __restrict__ res)
{
    tgemm_body<EPI, TB>(A, Bm, C, M, Nn, K, bias, res, blockIdx.y * 128, blockIdx.x * 128);
}

// fused Q,K,V projection: blockIdx.z selects weight/output
__global__ void __launch_bounds__(256, 2) tgemm_qkv(
    const float* __restrict__ A,
    const float* __restrict__ Wq, const float* __restrict__ Wk, const float* __restrict__ Wv,
    float* __restrict__ Cq, float* __restrict__ Ck, float* __restrict__ Cv)
{
    const float* Bm = (blockIdx.z == 0) ? Wq : (blockIdx.z == 1) ? Wk : Wv;
    float* C        = (blockIdx.z == 0) ? Cq : (blockIdx.z == 1) ? Ck : Cv;
    tgemm_body<EPI_NONE, false>(A, Bm, C, SB, ND, D_, nullptr, nullptr,
                                blockIdx.y * 128, blockIdx.x * 128);
}

// ---------------- ef[i,b,n,s] = (q + r_s_bias) . seg_embed[s] ----------------
__global__ void ef_kernel(const float* __restrict__ q, const float* __restrict__ rs,
                          const float* __restrict__ se, float* __restrict__ ef)
{
    int w = blockIdx.x * 4 + (threadIdx.x >> 5);   // over SB*NH
    int lane = threadIdx.x & 31;
    int row = w / NH, n = w % NH;
    int d0 = lane * 2;
    const float* qp = q + (size_t)row * ND + n * DH;
    float q0 = qp[d0]     + rs[n * DH + d0];
    float q1 = qp[d0 + 1] + rs[n * DH + d0 + 1];
    float s0 = q0 * se[(0 * NH + n) * DH + d0] + q1 * se[(0 * NH + n) * DH + d0 + 1];
    float s1 = q0 * se[(1 * NH + n) * DH + d0] + q1 * se[(1 * NH + n) * DH + d0 + 1];
    #pragma unroll
    for (int off = 16; off; off >>= 1) {
        s0 += __shfl_xor_sync(0xffffffffu, s0, off);
        s1 += __shfl_xor_sync(0xffffffffu, s1, off);
    }
    if (lane == 0) { ef[w * 2] = s0; ef[w * 2 + 1] = s1; }
}

// ---------------- fused flash attention: score + online softmax + P@V ----------------
// CTA = (head, i-tile of 64 rows). 16 warps: rg = wid&3 (row group of 16),
// sub = wid>>2 (owns score cols sub*16..+15 == its P@V k16 chunk; computes
// ac frags sub*2..sub*2+1 and Dloc cols sub*32..+31).
struct FlashSmem {
    unsigned QA[4][32][72];                 // Qw hi/lo, Qr hi/lo [kpair][row]
    union {
        unsigned KB[2][32][200];            // hi/lo [kpair][col: 0..63 K, 64..191 Krs]
        float    ored[64][68];              // final O reduction
    } kb;
    float dloc[64][132];                    // Dloc table
    unsigned VB[2][32][72];                 // V hi/lo [kpair(j)][d]
    float ef_s[64][2];
    float redmax[64][4];
    float redl[64][4];
};

__global__ void __launch_bounds__(512, 1) flash_attn(
    const float* __restrict__ q, const float* __restrict__ k, const float* __restrict__ kr,
    const float* __restrict__ v,
    const float* __restrict__ rw, const float* __restrict__ rr,
    const float* __restrict__ ef, const float* __restrict__ seg_mat,
    float* __restrict__ vec)
{
    extern __shared__ char smraw[];
    FlashSmem* sm = (FlashSmem*)smraw;
    const int head = blockIdx.x;
    const int b = head / NH, n = head % NH;
    const int i0 = (15 - blockIdx.y) * 64;      // longest-running CTAs first
    const int tid = threadIdx.x;
    const int wid = tid >> 5, lane = tid & 31;
    const int g = lane >> 2, tg = lane & 3;
    const int rg = wid & 3, sub = wid >> 2;
    const int rbase = rg * 16;

    // --- load Q once (Qw = q+rw, Qr = q+rr), split to bf16 hi/lo ---
    #pragma unroll
    for (int t = 0; t < 2; t++) {
        int job = tid + t * 512;
        int li = job >> 4, kq = (job & 15) * 4;
        const float* qp = q + ((size_t)((i0 + li) * B_ + b)) * ND + n * DH + kq;
        float4 qv = *(const float4*)qp;
        float4 wv = *(const float4*)(rw + n * DH + kq);
        float4 rv = *(const float4*)(rr + n * DH + kq);
        unsigned hi, lo; int kp = kq >> 1;
        split2(qv.x + wv.x, qv.y + wv.y, hi, lo); sm->QA[0][kp][li] = hi; sm->QA[1][kp][li] = lo;
        split2(qv.z + wv.z, qv.w + wv.w, hi, lo); sm->QA[0][kp+1][li] = hi; sm->QA[1][kp+1][li] = lo;
        split2(qv.x + rv.x, qv.y + rv.y, hi, lo); sm->QA[2][kp][li] = hi; sm->QA[3][kp][li] = lo;
        split2(qv.z + rv.z, qv.w + rv.w, hi, lo); sm->QA[2][kp+1][li] = hi; sm->QA[3][kp+1][li] = lo;
    }
    if (tid < 128)
        sm->ef_s[tid >> 1][tid & 1] =
            ef[((size_t)((i0 + (tid >> 1)) * B_ + b) * NH + n) * 2 + (tid & 1)];

    float m_r[2] = {-1e30f, -1e30f};
    float l_r[2] = {0.f, 0.f};
    float accO[8][4];
    #pragma unroll
    for (int f = 0; f < 8; f++)
        #pragma unroll
        for (int r = 0; r < 4; r++) accO[f][r] = 0.f;

    for (int j0 = 0; j0 <= i0; j0 += 64) {
        __syncthreads();   // previous iteration consumers done
        // --- load K tile (cols 0..63) ---
        #pragma unroll
        for (int t = 0; t < 2; t++) {
            int job = tid + t * 512;
            int li = job >> 4, dq = (job & 15) * 4;
            float4 kv = *(const float4*)(k + ((size_t)((j0 + li) * B_ + b)) * ND + n * DH + dq);
            unsigned hi, lo; int kp = dq >> 1;
            split2(kv.x, kv.y, hi, lo); sm->kb.KB[0][kp][li] = hi; sm->kb.KB[1][kp][li] = lo;
            split2(kv.z, kv.w, hi, lo); sm->kb.KB[0][kp+1][li] = hi; sm->kb.KB[1][kp+1][li] = lo;
        }
        // --- load Krs window (cols 64..191) ---
        const int r_base = S_ + j0 - i0 - 63;
        #pragma unroll
        for (int t = 0; t < 4; t++) {
            int job = tid + t * 512;
            int lr = job >> 4, dq = (job & 15) * 4;
            float4 kv = *(const float4*)(kr + ((size_t)((r_base + lr) * B_ + b)) * ND + n * DH + dq);
            unsigned hi, lo; int kp = dq >> 1, col = 64 + lr;
            split2(kv.x, kv.y, hi, lo); sm->kb.KB[0][kp][col] = hi; sm->kb.KB[1][kp][col] = lo;
            split2(kv.z, kv.w, hi, lo); sm->kb.KB[0][kp+1][col] = hi; sm->kb.KB[1][kp+1][col] = lo;
        }
        // --- load V tile transposed ---
        {
            int jp = tid >> 4, dq = (tid & 15) * 4;
            const float* vp0 = v + ((size_t)((j0 + 2 * jp) * B_ + b)) * ND + n * DH + dq;
            const float* vp1 = vp0 + (size_t)B_ * ND;
            float4 v0 = *(const float4*)vp0, v1 = *(const float4*)vp1;
            unsigned hi, lo;
            split2(v0.x, v1.x, hi, lo); sm->VB[0][jp][dq]     = hi; sm->VB[1][jp][dq]     = lo;
            split2(v0.y, v1.y, hi, lo); sm->VB[0][jp][dq + 1] = hi; sm->VB[1][jp][dq + 1] = lo;
            split2(v0.z, v1.z, hi, lo); sm->VB[0][jp][dq + 2] = hi; sm->VB[1][jp][dq + 2] = lo;
            split2(v0.w, v1.w, hi, lo); sm->VB[0][jp][dq + 3] = hi; sm->VB[1][jp][dq + 3] = lo;
        }
        __syncthreads();

        // --- score MMAs: ac (2 frags) + Dloc (4 frags) ---
        float aS[2][4], dS[4][4];
        #pragma unroll
        for (int f = 0; f < 2; f++)
            #pragma unroll
            for (int r = 0; r < 4; r++) aS[f][r] = 0.f;
        #pragma unroll
        for (int f = 0; f < 4; f++)
            #pragma unroll
            for (int r = 0; r < 4; r++) dS[f][r] = 0.f;

        #pragma unroll
        for (int kf = 0; kf < 4; kf++) {
            int kp = kf * 8;
            unsigned wh0 = sm->QA[0][kp + tg][rbase + g],     wh1 = sm->QA[0][kp + tg][rbase + g + 8];
            unsigned wh2 = sm->QA[0][kp + tg + 4][rbase + g], wh3 = sm->QA[0][kp + tg + 4][rbase + g + 8];
            unsigned wl0 = sm->QA[1][kp + tg][rbase + g],     wl1 = sm->QA[1][kp + tg][rbase + g + 8];
            unsigned wl2 = sm->QA[1][kp + tg + 4][rbase + g], wl3 = sm->QA[1][kp + tg + 4][rbase + g + 8];
            #pragma unroll
            for (int fa = 0; fa < 2; fa++) {
                int c = (sub * 2 + fa) * 8 + g;
                unsigned bh0 = sm->kb.KB[0][kp + tg][c], bh1 = sm->kb.KB[0][kp + tg + 4][c];
                unsigned bl0 = sm->kb.KB[1][kp + tg][c], bl1 = sm->kb.KB[1][kp + tg + 4][c];
                mma_bf16(aS[fa], wh0, wh1, wh2, wh3, bh0, bh1);
                mma_bf16(aS[fa], wh0, wh1, wh2, wh3, bl0, bl1);
                mma_bf16(aS[fa], wl0, wl1, wl2, wl3, bh0, bh1);
            }
            unsigned rh0 = sm->QA[2][kp + tg][rbase + g],     rh1 = sm->QA[2][kp + tg][rbase + g + 8];
            unsigned rh2 = sm->QA[2][kp + tg + 4][rbase + g], rh3 = sm->QA[2][kp + tg + 4][rbase + g + 8];
            unsigned rl0 = sm->QA[3][kp + tg][rbase + g],     rl1 = sm->QA[3][kp + tg][rbase + g + 8];
            unsigned rl2 = sm->QA[3][kp + tg + 4][rbase + g], rl3 = sm->QA[3][kp + tg + 4][rbase + g + 8];
            #pragma unroll
            for (int fd = 0; fd < 4; fd++) {
                int c = 64 + sub * 32 + fd * 8 + g;
                unsigned bh0 = sm->kb.KB[0][kp + tg][c], bh1 = sm->kb.KB[0][kp + tg + 4][c];
                unsigned bl0 = sm->kb.KB[1][kp + tg][c], bl1 = sm->kb.KB[1][kp + tg + 4][c];
                mma_bf16(dS[fd], rh0, rh1, rh2, rh3, bh0, bh1);
                mma_bf16(dS[fd], rh0, rh1, rh2, rh3, bl0, bl1);
                mma_bf16(dS[fd], rl0, rl1, rl2, rl3, bh0, bh1);
            }
        }
        // dump own Dloc frags
        #pragma unroll
        for (int fd = 0; fd < 4; fd++)
            #pragma unroll
            for (int r = 0; r < 4; r++)
                sm->dloc[rbase + g + (r >> 1) * 8][sub * 32 + fd * 8 + tg * 2 + (r & 1)] = dS[fd][r];
        __syncthreads();

        // --- combine + warp row max ---
        float s_v[2][4];
        float wmax[2] = {-3.0e38f, -3.0e38f};
        const bool diag = (j0 == i0);
        #pragma unroll
        for (int fa = 0; fa < 2; fa++)
            #pragma unroll
            for (int r = 0; r < 4; r++) {
                int li = rbase + g + (r >> 1) * 8;
                int lj = sub * 16 + fa * 8 + tg * 2 + (r & 1);
                int gi = i0 + li, gj = j0 + lj;
                float val;
                if (diag && gj > gi) {
                    val = -1e30f;
                } else {
                    float dl = sm->dloc[li][lj - li + 63];
                    float diff = seg_mat[(((size_t)gi * S_ + gj) * B_ + b) * 2 + 1];
                    float e0 = sm->ef_s[li][0], e1 = sm->ef_s[li][1];
                    val = (aS[fa][r] + dl + e0 + diff * (e1 - e0)) * 0.125f;
                }
                s_v[fa][r] = val;
                wmax[r >> 1] = fmaxf(wmax[r >> 1], val);
            }
        #pragma unroll
        for (int hh = 0; hh < 2; hh++) {
            wmax[hh] = fmaxf(wmax[hh], __shfl_xor_sync(0xffffffffu, wmax[hh], 1));
            wmax[hh] = fmaxf(wmax[hh], __shfl_xor_sync(0xffffffffu, wmax[hh], 2));
        }
        if (tg == 0) {
            sm->redmax[rbase + g][sub]     = wmax[0];
            sm->redmax[rbase + g + 8][sub] = wmax[1];
        }
        __syncthreads();

        // --- online softmax update ---
        float alpha_h[2];
        #pragma unroll
        for (int hh = 0; hh < 2; hh++) {
            int li = rbase + g + hh * 8;
            float tm = fmaxf(fmaxf(sm->redmax[li][0], sm->redmax[li][1]),
                             fmaxf(sm->redmax[li][2], sm->redmax[li][3]));
            float mnew = fmaxf(m_r[hh], tm);
            alpha_h[hh] = __expf(m_r[hh] - mnew);
            m_r[hh] = mnew;
            l_r[hh] *= alpha_h[hh];
        }
        #pragma unroll
        for (int f = 0; f < 8; f++) {
            accO[f][0] *= alpha_h[0]; accO[f][1] *= alpha_h[0];
            accO[f][2] *= alpha_h[1]; accO[f][3] *= alpha_h[1];
        }
        // --- P = exp(s - m), row partial sums, pack A-frags in-register ---
        float pv[2][4];
        float psum[2] = {0.f, 0.f};
        #pragma unroll
        for (int fa = 0; fa < 2; fa++)
            #pragma unroll
            for (int r = 0; r < 4; r++) {
                float p = __expf(s_v[fa][r] - m_r[r >> 1]);
                pv[fa][r] = p;
                psum[r >> 1] += p;
            }
        #pragma unroll
        for (int hh = 0; hh < 2; hh++) {
            psum[hh] += __shfl_xor_sync(0xffffffffu, psum[hh], 1);
            psum[hh] += __shfl_xor_sync(0xffffffffu, psum[hh], 2);
            l_r[hh] += psum[hh];
        }
        unsigned ph[4], pl[4];
        split2(pv[0][0], pv[0][1], ph[0], pl[0]);
        split2(pv[0][2], pv[0][3], ph[1], pl[1]);
        split2(pv[1][0], pv[1][1], ph[2], pl[2]);
        split2(pv[1][2], pv[1][3], ph[3], pl[3]);
        // --- P @ V (this warp's k16 chunk = V rows sub*16..+15) ---
        const int kpb = sub * 8;
        #pragma unroll
        for (int f = 0; f < 8; f++) {
            int c = f * 8 + g;
            unsigned bh0 = sm->VB[0][kpb + tg][c], bh1 = sm->VB[0][kpb + tg + 4][c];
            unsigned bl0 = sm->VB[1][kpb + tg][c], bl1 = sm->VB[1][kpb + tg + 4][c];
            mma_bf16(accO[f], ph[0], ph[1], ph[2], ph[3], bh0, bh1);
            mma_bf16(accO[f], ph[0], ph[1], ph[2], ph[3], bl0, bl1);
            mma_bf16(accO[f], pl[0], pl[1], pl[2], pl[3], bh0, bh1);
        }
    }

    // --- final: reduce K-split partials deterministically, normalize, store ---
    __syncthreads();
    if (tg == 0) {
        sm->redl[rbase + g][sub]     = l_r[0];
        sm->redl[rbase + g + 8][sub] = l_r[1];
    }
    #pragma unroll
    for (int s = 0; s < 4; s++) {
        if (sub == s) {
            #pragma unroll
            for (int f = 0; f < 8; f++)
                #pragma unroll
                for (int r = 0; r < 4; r++) {
                    int row = rbase + g + (r >> 1) * 8;
                    int col = f * 8 + tg * 2 + (r & 1);
                    if (s == 0) sm->kb.ored[row][col] = accO[f][r];
                    else        sm->kb.ored[row][col] += accO[f][r];
                }
        }
        __syncthreads();
    }
    #pragma unroll
    for (int t = 0; t < 8; t++) {
        int job = tid + t * 512;
        int row = job >> 6, col = job & 63;
        float lt = sm->redl[row][0] + sm->redl[row][1] + sm->redl[row][2] + sm->redl[row][3];
        vec[((size_t)((i0 + row) * B_ + b)) * ND + n * DH + col] = sm->kb.ored[row][col] / lt;
    }
}

// ---------------- layernorm (optional fused residual add) ----------------
__global__ void ln_kernel(const float* __restrict__ x, const float* __restrict__ res,
                          const float* __restrict__ g, const float* __restrict__ b,
                          float* __restrict__ out)
{
    __shared__ float red[256];
    const int row = blockIdx.x, tid = threadIdx.x;
    const float* xr = x + (size_t)row * D_;
    float v[4];
    float s = 0.f;
    #pragma unroll
    for (int t = 0; t < 4; t++) {
        int d = tid + t * 256;
        v[t] = xr[d];
        if (res) v[t] += res[(size_t)row * D_ + d];
        s += v[t];
    }
    red[tid] = s; __syncthreads();
    for (int o = 128; o > 0; o >>= 1) { if (tid < o) red[tid] += red[tid + o]; __syncthreads(); }
    float mean = red[0] * (1.f / D_);
    __syncthreads();
    s = 0.f;
    #pragma unroll
    for (int t = 0; t < 4; t++) { float d2 = v[t] - mean; s += d2 * d2; }
    red[tid] = s; __syncthreads();
    for (int o = 128; o > 0; o >>= 1) { if (tid < o) red[tid] += red[tid + o]; __syncthreads(); }
    float inv = rsqrtf(red[0] * (1.f / D_) + 1e-12f);
    #pragma unroll
    for (int t = 0; t < 4; t++) {
        int d = tid + t * 256;
        out[(size_t)row * D_ + d] = (v[t] - mean) * inv * g[d] + b[d];
    }
}

// ---------------- host ----------------
static float* sym_addr(const void* sym) {
    void* p = nullptr;
    cudaGetSymbolAddress(&p, sym);
    return (float*)p;
}

extern "C" void kernel_launch(void* const* d_in, const int* in_sizes, int n_in,
                              void* d_out, int out_size)
{
    (void)in_sizes; (void)n_in; (void)out_size;
    const float* h         = (const float*)d_in[0];
    const float* pos_emb   = (const float*)d_in[1];
    const float* seg_mat   = (const float*)d_in[3];
    const float* Wq        = (const float*)d_in[4];
    const float* Wk        = (const float*)d_in[5];
    const float* Wv        = (const float*)d_in[6];
    const float* Wo        = (const float*)d_in[7];
    const float* Wr        = (const float*)d_in[8];
    const float* rw        = (const float*)d_in[9];
    const float* rr        = (const float*)d_in[10];
    const float* rs        = (const float*)d_in[11];
    const float* se        = (const float*)d_in[12];
    const float* ln1g      = (const float*)d_in[13];
    const float* ln1b      = (const float*)d_in[14];
    const float* w1        = (const float*)d_in[15];
    const float* b1        = (const float*)d_in[16];
    const float* w2        = (const float*)d_in[17];
    const float* b2        = (const float*)d_in[18];
    const float* ln2g      = (const float*)d_in[19];
    const float* ln2b      = (const float*)d_in[20];
    float* out = (float*)d_out;

    float* gq    = sym_addr(g_q);
    float* gk    = sym_addr(g_k);
    float* gv    = sym_addr(g_v);
    float* gkr   = sym_addr(g_kr);
    float* gef   = sym_addr(g_ef);
    float* gvec  = sym_addr(g_vec);
    float* gattn = sym_addr(g_attn);
    float* gx    = sym_addr(g_x);
    float* gf    = sym_addr(g_f);
    float* gf2   = sym_addr(g_f2);
    float* gbuf  = sym_addr(g_buf);

    static bool attr_set = false;
    if (!attr_set) {
        cudaFuncSetAttribute(flash_attn, cudaFuncAttributeMaxDynamicSharedMemorySize,
                             (int)sizeof(FlashSmem));
        attr_set = true;
    }

    for (int l = 0; l < 2; l++) {
        const float* cur = (l == 0) ? h : gbuf;
        float* nxt = (l == 0) ? gbuf : out;
        const size_t woff = (size_t)l * D_ * ND;

        tgemm_qkv<<<dim3(ND / 128, SB / 128, 3), 256>>>(
            cur, Wq + woff, Wk + woff, Wv + woff, gq, gk, gv);
        tgemm<EPI_NONE, false><<<dim3(ND / 128, RB / 128), 256>>>(
            pos_emb, Wr + woff, gkr, RB, ND, D_, nullptr, nullptr);

        ef_kernel<<<SB * NH / 4, 128>>>(gq, rs + l * NH * DH, se + l * 2 * NH * DH, gef);

        flash_attn<<<dim3(NHEADS, S_ / 64), 512, sizeof(FlashSmem)>>>(
            gq, gk, gkr, gv, rw + l * NH * DH, rr + l * NH * DH,
            gef, seg_mat, gvec);

        tgemm<EPI_RES, true><<<dim3(D_ / 128, SB / 128), 256>>>(
            gvec, Wo + woff, gattn, SB, D_, ND, nullptr, cur);

        ln_kernel<<<SB, 256>>>(gattn, nullptr, ln1g + l * D_, ln1b + l * D_, gx);

        tgemm<EPI_BIAS_GELU, false><<<dim3(DI_ / 128, SB / 128), 256>>>(
            gx, w1 + (size_t)l * D_ * DI_, gf, SB, DI_, D_, b1 + l * DI_, nullptr);

        tgemm<EPI_BIAS, false><<<dim3(D_ / 128, SB / 128), 256>>>(
            gf, w2 + (size_t)l * DI_ * D_, gf2, SB, D_, DI_, b2 + l * D_, nullptr);

        ln_kernel<<<SB, 256>>>(gf2, gx, ln2g + l * D_, ln2b + l * D_, nxt);
    }
}

// round 7
// speedup vs baseline: 2.8971x; 1.0980x over previous
#include <cuda_runtime.h>
#include <math.h>

#define S_   1024
#define B_   2
#define D_   1024
#define NH   16
#define DH   64
#define DI_  4096
#define R_   2048
#define SB   (S_*B_)          // 2048
#define RB   (R_*B_)          // 4096
#define ND   (NH*DH)          // 1024
#define NHEADS (B_*NH)        // 32
#define KRR  1152             // kr rows actually consumed (max index 1087)

// ---------------- scratch (device globals; no allocation allowed) ----------------
__device__ float g_q   [SB*ND];
__device__ float g_k   [SB*ND];
__device__ float g_v   [SB*ND];
__device__ float g_kr  [RB*ND];
__device__ float g_ef  [SB*NH*2];
__device__ float g_vec [SB*ND];
__device__ float g_attn[SB*ND];
__device__ float g_x   [SB*ND];
__device__ float g_f   [SB*DI_];
__device__ float g_f2  [SB*ND];
__device__ float g_buf [SB*ND];

enum { EPI_NONE = 0, EPI_BIAS = 1, EPI_BIAS_GELU = 2, EPI_RES = 3 };

__device__ __forceinline__ float gelu_f(float x) {
    return 0.5f * x * (1.0f + erff(x * 0.7071067811865476f));
}

// ---------------- bf16 split helpers ----------------
__device__ __forceinline__ void split2(float x0, float x1, unsigned& hi, unsigned& lo) {
    unsigned h;
    asm("cvt.rn.bf16x2.f32 %0, %1, %2;" : "=r"(h) : "f"(x1), "f"(x0));
    float h0 = __uint_as_float(h << 16);
    float h1 = __uint_as_float(h & 0xffff0000u);
    float r0 = x0 - h0;
    float r1 = x1 - h1;
    unsigned l;
    asm("cvt.rn.bf16x2.f32 %0, %1, %2;" : "=r"(l) : "f"(r1), "f"(r0));
    hi = h; lo = l;
}

__device__ __forceinline__ void mma_bf16(float* c,
    unsigned a0, unsigned a1, unsigned a2, unsigned a3, unsigned b0, unsigned b1) {
    asm volatile(
        "mma.sync.aligned.m16n8k16.row.col.f32.bf16.bf16.f32 "
        "{%0,%1,%2,%3}, {%4,%5,%6,%7}, {%8,%9}, {%0,%1,%2,%3};\n"
        : "+f"(c[0]), "+f"(c[1]), "+f"(c[2]), "+f"(c[3])
        : "r"(a0), "r"(a1), "r"(a2), "r"(a3), "r"(b0), "r"(b1));
}

// ---------------- tensor-core 128x128 GEMM body, bf16 split, NN / NT ----------------
template<int EPI, bool TB>
__device__ __forceinline__ void tgemm_body(
    const float* __restrict__ A, const float* __restrict__ Bm, float* __restrict__ C,
    int M, int Nn, int K, const float* __restrict__ bias, const float* __restrict__ res,
    int m0, int n0)
{
    __shared__ unsigned Ah[2][8][136], Al[2][8][136];
    __shared__ unsigned Bh[2][8][136], Bl[2][8][136];
    const int tid = threadIdx.x;
    const int wid = tid >> 5, lane = tid & 31;
    const int wm = (wid >> 2) * 64;
    const int wn = (wid & 3) * 32;
    const int g  = lane >> 2;
    const int tg = lane & 3;

    const int lm = tid >> 1, lq = (tid & 1) * 8;
    const int bk = tid >> 5, bn = (tid & 31) * 4;

    float acc[4][4][4];
    #pragma unroll
    for (int mt = 0; mt < 4; mt++)
        #pragma unroll
        for (int nt = 0; nt < 4; nt++)
            #pragma unroll
            for (int r = 0; r < 4; r++) acc[mt][nt][r] = 0.f;

    float a_st[8], b_st[8];

    auto load_slab = [&](int k0) {
        *(float4*)(a_st)     = *(const float4*)(A + (size_t)(m0 + lm) * K + k0 + lq);
        *(float4*)(a_st + 4) = *(const float4*)(A + (size_t)(m0 + lm) * K + k0 + lq + 4);
        if (TB) {
            *(float4*)(b_st)     = *(const float4*)(Bm + (size_t)(n0 + lm) * K + k0 + lq);
            *(float4*)(b_st + 4) = *(const float4*)(Bm + (size_t)(n0 + lm) * K + k0 + lq + 4);
        } else {
            *(float4*)(b_st)     = *(const float4*)(Bm + (size_t)(k0 + 2 * bk) * Nn + n0 + bn);
            *(float4*)(b_st + 4) = *(const float4*)(Bm + (size_t)(k0 + 2 * bk + 1) * Nn + n0 + bn);
        }
    };

    auto store_slab = [&](int s) {
        #pragma unroll
        for (int j = 0; j < 4; j++) {
            unsigned hi, lo;
            split2(a_st[2 * j], a_st[2 * j + 1], hi, lo);
            Ah[s][(lq >> 1) + j][lm] = hi;
            Al[s][(lq >> 1) + j][lm] = lo;
        }
        if (TB) {
            #pragma unroll
            for (int j = 0; j < 4; j++) {
                unsigned hi, lo;
                split2(b_st[2 * j], b_st[2 * j + 1], hi, lo);
                Bh[s][(lq >> 1) + j][lm] = hi;
                Bl[s][(lq >> 1) + j][lm] = lo;
            }
        } else {
            #pragma unroll
            for (int j = 0; j < 4; j++) {
                unsigned hi, lo;
                split2(b_st[j], b_st[4 + j], hi, lo);
                Bh[s][bk][bn + j] = hi;
                Bl[s][bk][bn + j] = lo;
            }
        }
    };

    auto compute = [&](int s) {
        unsigned bh0[4], bh1[4], bl0[4], bl1[4];
        #pragma unroll
        for (int nt = 0; nt < 4; nt++) {
            int c = wn + nt * 8 + g;
            bh0[nt] = Bh[s][tg][c];     bh1[nt] = Bh[s][tg + 4][c];
            bl0[nt] = Bl[s][tg][c];     bl1[nt] = Bl[s][tg + 4][c];
        }
        #pragma unroll
        for (int mt = 0; mt < 4; mt++) {
            int r0c = wm + mt * 16 + g;
            unsigned ah0 = Ah[s][tg][r0c],     ah1 = Ah[s][tg][r0c + 8];
            unsigned ah2 = Ah[s][tg + 4][r0c], ah3 = Ah[s][tg + 4][r0c + 8];
            unsigned al0 = Al[s][tg][r0c],     al1 = Al[s][tg][r0c + 8];
            unsigned al2 = Al[s][tg + 4][r0c], al3 = Al[s][tg + 4][r0c + 8];
            #pragma unroll
            for (int nt = 0; nt < 4; nt++) {
                float* c = acc[mt][nt];
                mma_bf16(c, ah0, ah1, ah2, ah3, bh0[nt], bh1[nt]);
                mma_bf16(c, ah0, ah1, ah2, ah3, bl0[nt], bl1[nt]);
                mma_bf16(c, al0, al1, al2, al3, bh0[nt], bh1[nt]);
            }
        }
    };

    const int nslab = K >> 4;
    load_slab(0);
    store_slab(0);
    __syncthreads();
    for (int kt = 0; kt < nslab; kt++) {
        if (kt + 1 < nslab) load_slab((kt + 1) << 4);
        compute(kt & 1);
        if (kt + 1 < nslab) store_slab((kt + 1) & 1);
        __syncthreads();
    }

    #pragma unroll
    for (int mt = 0; mt < 4; mt++) {
        int r0 = m0 + wm + mt * 16 + g;
        #pragma unroll
        for (int nt = 0; nt < 4; nt++) {
            int c0 = n0 + wn + nt * 8 + tg * 2;
            #pragma unroll
            for (int r = 0; r < 4; r++) {
                int mm = r0 + (r >> 1) * 8;
                int nn = c0 + (r & 1);
                float v = acc[mt][nt][r];
                if (EPI == EPI_BIAS || EPI == EPI_BIAS_GELU) v += bias[nn];
                if (EPI == EPI_BIAS_GELU) v = gelu_f(v);
                if (EPI == EPI_RES) v += res[(size_t)mm * Nn + nn];
                C[(size_t)mm * Nn + nn] = v;
            }
        }
    }
}

template<int EPI, bool TB>
__global__ void __launch_bounds__(256, 2) tgemm(
    const float* __restrict__ A, const float* __restrict__ Bm, float* __restrict__ C,
    int M, int Nn, int K, const float* __restrict__ bias, const float* __restrict__ res)
{
    tgemm_body<EPI, TB>(A, Bm, C, M, Nn, K, bias, res, blockIdx.y * 128, blockIdx.x * 128);
}

// fused Q,K,V projection: blockIdx.z selects weight/output
__global__ void __launch_bounds__(256, 2) tgemm_qkv(
    const float* __restrict__ A,
    const float* __restrict__ Wq, const float* __restrict__ Wk, const float* __restrict__ Wv,
    float* __restrict__ Cq, float* __restrict__ Ck, float* __restrict__ Cv)
{
    const float* Bm = (blockIdx.z == 0) ? Wq : (blockIdx.z == 1) ? Wk : Wv;
    float* C        = (blockIdx.z == 0) ? Cq : (blockIdx.z == 1) ? Ck : Cv;
    tgemm_body<EPI_NONE, false>(A, Bm, C, SB, ND, D_, nullptr, nullptr,
                                blockIdx.y * 128, blockIdx.x * 128);
}

// ---------------- ef[i,b,n,s] = (q + r_s_bias) . seg_embed[s] ----------------
__global__ void ef_kernel(const float* __restrict__ q, const float* __restrict__ rs,
                          const float* __restrict__ se, float* __restrict__ ef)
{
    int w = blockIdx.x * 4 + (threadIdx.x >> 5);   // over SB*NH
    int lane = threadIdx.x & 31;
    int row = w / NH, n = w % NH;
    int d0 = lane * 2;
    const float* qp = q + (size_t)row * ND + n * DH;
    float q0 = qp[d0]     + rs[n * DH + d0];
    float q1 = qp[d0 + 1] + rs[n * DH + d0 + 1];
    float s0 = q0 * se[(0 * NH + n) * DH + d0] + q1 * se[(0 * NH + n) * DH + d0 + 1];
    float s1 = q0 * se[(1 * NH + n) * DH + d0] + q1 * se[(1 * NH + n) * DH + d0 + 1];
    #pragma unroll
    for (int off = 16; off; off >>= 1) {
        s0 += __shfl_xor_sync(0xffffffffu, s0, off);
        s1 += __shfl_xor_sync(0xffffffffu, s1, off);
    }
    if (lane == 0) { ef[w * 2] = s0; ef[w * 2 + 1] = s1; }
}

// ---------------- fused flash attention: score + online softmax + P@V ----------------
// CTA = (head, i-tile of 64 rows). 16 warps: rg = wid&3 (row group of 16),
// sub = wid>>2 (owns score cols sub*16..+15 == its P@V k16 chunk).
// Krs kept in a 128-col ring: kr row m lives at phys col 64 + (m & 127).
struct FlashSmem {
    unsigned QA[4][32][72];                 // Qw hi/lo, Qr hi/lo [kpair][row]
    union {
        unsigned KB[2][32][200];            // hi/lo [kpair][col: 0..63 K, 64..191 Krs ring]
        float    ored[64][68];              // final O reduction
    } kb;
    float dloc[64][132];                    // Dloc table (logical u = lj-li+64)
    unsigned VB[2][32][72];                 // V hi/lo [kpair(j)][d]
    float ef_s[64][2];
    float redmax[64][4];
    float redl[64][4];
};

__global__ void __launch_bounds__(512, 1) flash_attn(
    const float* __restrict__ q, const float* __restrict__ k, const float* __restrict__ kr,
    const float* __restrict__ v,
    const float* __restrict__ rw, const float* __restrict__ rr,
    const float* __restrict__ ef, const float* __restrict__ seg_mat,
    float* __restrict__ vec)
{
    extern __shared__ char smraw[];
    FlashSmem* sm = (FlashSmem*)smraw;
    const int head = blockIdx.x;
    const int b = head / NH, n = head % NH;
    const int i0 = (15 - blockIdx.y) * 64;      // longest-running CTAs first
    const int tid = threadIdx.x;
    const int wid = tid >> 5, lane = tid & 31;
    const int g = lane >> 2, tg = lane & 3;
    const int rg = wid & 3, sub = wid >> 2;
    const int rbase = rg * 16;

    // --- load Q once (Qw = q+rw, Qr = q+rr), split to bf16 hi/lo ---
    #pragma unroll
    for (int t = 0; t < 2; t++) {
        int job = tid + t * 512;
        int li = job >> 4, kq = (job & 15) * 4;
        const float* qp = q + ((size_t)((i0 + li) * B_ + b)) * ND + n * DH + kq;
        float4 qv = *(const float4*)qp;
        float4 wv = *(const float4*)(rw + n * DH + kq);
        float4 rv = *(const float4*)(rr + n * DH + kq);
        unsigned hi, lo; int kp = kq >> 1;
        split2(qv.x + wv.x, qv.y + wv.y, hi, lo); sm->QA[0][kp][li] = hi; sm->QA[1][kp][li] = lo;
        split2(qv.z + wv.z, qv.w + wv.w, hi, lo); sm->QA[0][kp+1][li] = hi; sm->QA[1][kp+1][li] = lo;
        split2(qv.x + rv.x, qv.y + rv.y, hi, lo); sm->QA[2][kp][li] = hi; sm->QA[3][kp][li] = lo;
        split2(qv.z + rv.z, qv.w + rv.w, hi, lo); sm->QA[2][kp+1][li] = hi; sm->QA[3][kp+1][li] = lo;
    }
    if (tid < 128)
        sm->ef_s[tid >> 1][tid & 1] =
            ef[((size_t)((i0 + (tid >> 1)) * B_ + b) * NH + n) * 2 + (tid & 1)];

    float m_r[2] = {-1e30f, -1e30f};
    float l_r[2] = {0.f, 0.f};
    float accO[8][4];
    #pragma unroll
    for (int f = 0; f < 8; f++)
        #pragma unroll
        for (int r = 0; r < 4; r++) accO[f][r] = 0.f;

    // loader index precompute
    const int lK_li = tid >> 4, lK_dq = (tid & 15) * 4;   // K/Krs loaders
    const int lV_jp = tid >> 4, lV_dq = (tid & 15) * 4;   // V loader

    for (int j0 = 0; j0 <= i0; j0 += 64) {
        const int w = S_ + j0 - i0 - 64;        // ring window start (mult of 64)
        const int ofs = w & 127;
        const bool first = (j0 == 0);
        __syncthreads();   // previous iteration consumers done

        // ===== issue ALL gmem loads first =====
        float4 kv0 = *(const float4*)(k + ((size_t)((j0 + lK_li) * B_ + b)) * ND + n * DH + lK_dq);
        float4 kv1 = *(const float4*)(k + ((size_t)((j0 + lK_li + 32) * B_ + b)) * ND + n * DH + lK_dq);
        const float* vp0 = v + ((size_t)((j0 + 2 * lV_jp) * B_ + b)) * ND + n * DH + lV_dq;
        float4 vv0 = *(const float4*)vp0;
        float4 vv1 = *(const float4*)(vp0 + (size_t)B_ * ND);
        const int mstart = first ? w : (w + 64);
        float4 rv0 = *(const float4*)(kr + ((size_t)((mstart + lK_li) * B_ + b)) * ND + n * DH + lK_dq);
        float4 rv1 = *(const float4*)(kr + ((size_t)((mstart + lK_li + 32) * B_ + b)) * ND + n * DH + lK_dq);
        float4 rv2, rv3;
        if (first) {
            rv2 = *(const float4*)(kr + ((size_t)((mstart + lK_li + 64) * B_ + b)) * ND + n * DH + lK_dq);
            rv3 = *(const float4*)(kr + ((size_t)((mstart + lK_li + 96) * B_ + b)) * ND + n * DH + lK_dq);
        }
        // seg_mat prefetch for this warp's 8 score elems
        float segv[2][4];
        #pragma unroll
        for (int fa = 0; fa < 2; fa++)
            #pragma unroll
            for (int r = 0; r < 4; r++) {
                int gi = i0 + rbase + g + (r >> 1) * 8;
                int gj = j0 + sub * 16 + fa * 8 + tg * 2 + (r & 1);
                segv[fa][r] = __ldg(&seg_mat[(((size_t)gi * S_ + gj) * B_ + b) * 2 + 1]);
            }

        // ===== split + store =====
        {
            unsigned hi, lo; int kp = lK_dq >> 1;
            split2(kv0.x, kv0.y, hi, lo); sm->kb.KB[0][kp][lK_li] = hi; sm->kb.KB[1][kp][lK_li] = lo;
            split2(kv0.z, kv0.w, hi, lo); sm->kb.KB[0][kp+1][lK_li] = hi; sm->kb.KB[1][kp+1][lK_li] = lo;
            split2(kv1.x, kv1.y, hi, lo); sm->kb.KB[0][kp][lK_li + 32] = hi; sm->kb.KB[1][kp][lK_li + 32] = lo;
            split2(kv1.z, kv1.w, hi, lo); sm->kb.KB[0][kp+1][lK_li + 32] = hi; sm->kb.KB[1][kp+1][lK_li + 32] = lo;
            int c0 = 64 + ((mstart + lK_li) & 127);
            int c1 = 64 + ((mstart + lK_li + 32) & 127);
            split2(rv0.x, rv0.y, hi, lo); sm->kb.KB[0][kp][c0] = hi; sm->kb.KB[1][kp][c0] = lo;
            split2(rv0.z, rv0.w, hi, lo); sm->kb.KB[0][kp+1][c0] = hi; sm->kb.KB[1][kp+1][c0] = lo;
            split2(rv1.x, rv1.y, hi, lo); sm->kb.KB[0][kp][c1] = hi; sm->kb.KB[1][kp][c1] = lo;
            split2(rv1.z, rv1.w, hi, lo); sm->kb.KB[0][kp+1][c1] = hi; sm->kb.KB[1][kp+1][c1] = lo;
            if (first) {
                int c2 = 64 + ((mstart + lK_li + 64) & 127);
                int c3 = 64 + ((mstart + lK_li + 96) & 127);
                split2(rv2.x, rv2.y, hi, lo); sm->kb.KB[0][kp][c2] = hi; sm->kb.KB[1][kp][c2] = lo;
                split2(rv2.z, rv2.w, hi, lo); sm->kb.KB[0][kp+1][c2] = hi; sm->kb.KB[1][kp+1][c2] = lo;
                split2(rv3.x, rv3.y, hi, lo); sm->kb.KB[0][kp][c3] = hi; sm->kb.KB[1][kp][c3] = lo;
                split2(rv3.z, rv3.w, hi, lo); sm->kb.KB[0][kp+1][c3] = hi; sm->kb.KB[1][kp+1][c3] = lo;
            }
            split2(vv0.x, vv1.x, hi, lo); sm->VB[0][lV_jp][lV_dq]     = hi; sm->VB[1][lV_jp][lV_dq]     = lo;
            split2(vv0.y, vv1.y, hi, lo); sm->VB[0][lV_jp][lV_dq + 1] = hi; sm->VB[1][lV_jp][lV_dq + 1] = lo;
            split2(vv0.z, vv1.z, hi, lo); sm->VB[0][lV_jp][lV_dq + 2] = hi; sm->VB[1][lV_jp][lV_dq + 2] = lo;
            split2(vv0.w, vv1.w, hi, lo); sm->VB[0][lV_jp][lV_dq + 3] = hi; sm->VB[1][lV_jp][lV_dq + 3] = lo;
        }
        __syncthreads();

        // --- score MMAs: ac (2 frags) + Dloc (4 frags) ---
        float aS[2][4], dS[4][4];
        #pragma unroll
        for (int f = 0; f < 2; f++)
            #pragma unroll
            for (int r = 0; r < 4; r++) aS[f][r] = 0.f;
        #pragma unroll
        for (int f = 0; f < 4; f++)
            #pragma unroll
            for (int r = 0; r < 4; r++) dS[f][r] = 0.f;

        #pragma unroll
        for (int kf = 0; kf < 4; kf++) {
            int kp = kf * 8;
            unsigned wh0 = sm->QA[0][kp + tg][rbase + g],     wh1 = sm->QA[0][kp + tg][rbase + g + 8];
            unsigned wh2 = sm->QA[0][kp + tg + 4][rbase + g], wh3 = sm->QA[0][kp + tg + 4][rbase + g + 8];
            unsigned wl0 = sm->QA[1][kp + tg][rbase + g],     wl1 = sm->QA[1][kp + tg][rbase + g + 8];
            unsigned wl2 = sm->QA[1][kp + tg + 4][rbase + g], wl3 = sm->QA[1][kp + tg + 4][rbase + g + 8];
            #pragma unroll
            for (int fa = 0; fa < 2; fa++) {
                int c = (sub * 2 + fa) * 8 + g;
                unsigned bh0 = sm->kb.KB[0][kp + tg][c], bh1 = sm->kb.KB[0][kp + tg + 4][c];
                unsigned bl0 = sm->kb.KB[1][kp + tg][c], bl1 = sm->kb.KB[1][kp + tg + 4][c];
                mma_bf16(aS[fa], wh0, wh1, wh2, wh3, bh0, bh1);
                mma_bf16(aS[fa], wh0, wh1, wh2, wh3, bl0, bl1);
                mma_bf16(aS[fa], wl0, wl1, wl2, wl3, bh0, bh1);
            }
            unsigned rh0 = sm->QA[2][kp + tg][rbase + g],     rh1 = sm->QA[2][kp + tg][rbase + g + 8];
            unsigned rh2 = sm->QA[2][kp + tg + 4][rbase + g], rh3 = sm->QA[2][kp + tg + 4][rbase + g + 8];
            unsigned rl0 = sm->QA[3][kp + tg][rbase + g],     rl1 = sm->QA[3][kp + tg][rbase + g + 8];
            unsigned rl2 = sm->QA[3][kp + tg + 4][rbase + g], rl3 = sm->QA[3][kp + tg + 4][rbase + g + 8];
            #pragma unroll
            for (int fd = 0; fd < 4; fd++) {
                int c = 64 + ((ofs + sub * 32 + fd * 8) & 127) + g;
                unsigned bh0 = sm->kb.KB[0][kp + tg][c], bh1 = sm->kb.KB[0][kp + tg + 4][c];
                unsigned bl0 = sm->kb.KB[1][kp + tg][c], bl1 = sm->kb.KB[1][kp + tg + 4][c];
                mma_bf16(dS[fd], rh0, rh1, rh2, rh3, bh0, bh1);
                mma_bf16(dS[fd], rh0, rh1, rh2, rh3, bl0, bl1);
                mma_bf16(dS[fd], rl0, rl1, rl2, rl3, bh0, bh1);
            }
        }
        // dump own Dloc frags (logical u index)
        #pragma unroll
        for (int fd = 0; fd < 4; fd++)
            #pragma unroll
            for (int r = 0; r < 4; r++)
                sm->dloc[rbase + g + (r >> 1) * 8][sub * 32 + fd * 8 + tg * 2 + (r & 1)] = dS[fd][r];
        __syncthreads();

        // --- combine + warp row max ---
        float s_v[2][4];
        float wmax[2] = {-3.0e38f, -3.0e38f};
        const bool diag = (j0 == i0);
        #pragma unroll
        for (int fa = 0; fa < 2; fa++)
            #pragma unroll
            for (int r = 0; r < 4; r++) {
                int li = rbase + g + (r >> 1) * 8;
                int lj = sub * 16 + fa * 8 + tg * 2 + (r & 1);
                float val;
                if (diag && lj > li) {
                    val = -1e30f;
                } else {
                    float dl = sm->dloc[li][lj - li + 64];
                    float e0 = sm->ef_s[li][0], e1 = sm->ef_s[li][1];
                    val = (aS[fa][r] + dl + e0 + segv[fa][r] * (e1 - e0)) * 0.125f;
                }
                s_v[fa][r] = val;
                wmax[r >> 1] = fmaxf(wmax[r >> 1], val);
            }
        #pragma unroll
        for (int hh = 0; hh < 2; hh++) {
            wmax[hh] = fmaxf(wmax[hh], __shfl_xor_sync(0xffffffffu, wmax[hh], 1));
            wmax[hh] = fmaxf(wmax[hh], __shfl_xor_sync(0xffffffffu, wmax[hh], 2));
        }
        if (tg == 0) {
            sm->redmax[rbase + g][sub]     = wmax[0];
            sm->redmax[rbase + g + 8][sub] = wmax[1];
        }
        __syncthreads();

        // --- online softmax update ---
        float alpha_h[2];
        #pragma unroll
        for (int hh = 0; hh < 2; hh++) {
            int li = rbase + g + hh * 8;
            float tm = fmaxf(fmaxf(sm->redmax[li][0], sm->redmax[li][1]),
                             fmaxf(sm->redmax[li][2], sm->redmax[li][3]));
            float mnew = fmaxf(m_r[hh], tm);
            alpha_h[hh] = __expf(m_r[hh] - mnew);
            m_r[hh] = mnew;
            l_r[hh] *= alpha_h[hh];
        }
        #pragma unroll
        for (int f = 0; f < 8; f++) {
            accO[f][0] *= alpha_h[0]; accO[f][1] *= alpha_h[0];
            accO[f][2] *= alpha_h[1]; accO[f][3] *= alpha_h[1];
        }
        // --- P = exp(s - m), row partial sums, pack A-frags in-register ---
        float pv[2][4];
        float psum[2] = {0.f, 0.f};
        #pragma unroll
        for (int fa = 0; fa < 2; fa++)
            #pragma unroll
            for (int r = 0; r < 4; r++) {
                float p = __expf(s_v[fa][r] - m_r[r >> 1]);
                pv[fa][r] = p;
                psum[r >> 1] += p;
            }
        #pragma unroll
        for (int hh = 0; hh < 2; hh++) {
            psum[hh] += __shfl_xor_sync(0xffffffffu, psum[hh], 1);
            psum[hh] += __shfl_xor_sync(0xffffffffu, psum[hh], 2);
            l_r[hh] += psum[hh];
        }
        unsigned ph[4], pl[4];
        split2(pv[0][0], pv[0][1], ph[0], pl[0]);
        split2(pv[0][2], pv[0][3], ph[1], pl[1]);
        split2(pv[1][0], pv[1][1], ph[2], pl[2]);
        split2(pv[1][2], pv[1][3], ph[3], pl[3]);
        // --- P @ V (this warp's k16 chunk = V rows sub*16..+15) ---
        const int kpb = sub * 8;
        #pragma unroll
        for (int f = 0; f < 8; f++) {
            int c = f * 8 + g;
            unsigned bh0 = sm->VB[0][kpb + tg][c], bh1 = sm->VB[0][kpb + tg + 4][c];
            unsigned bl0 = sm->VB[1][kpb + tg][c], bl1 = sm->VB[1][kpb + tg + 4][c];
            mma_bf16(accO[f], ph[0], ph[1], ph[2], ph[3], bh0, bh1);
            mma_bf16(accO[f], ph[0], ph[1], ph[2], ph[3], bl0, bl1);
            mma_bf16(accO[f], pl[0], pl[1], pl[2], pl[3], bh0, bh1);
        }
    }

    // --- final: reduce K-split partials deterministically, normalize, store ---
    __syncthreads();
    if (tg == 0) {
        sm->redl[rbase + g][sub]     = l_r[0];
        sm->redl[rbase + g + 8][sub] = l_r[1];
    }
    #pragma unroll
    for (int s = 0; s < 4; s++) {
        if (sub == s) {
            #pragma unroll
            for (int f = 0; f < 8; f++)
                #pragma unroll
                for (int r = 0; r < 4; r++) {
                    int row = rbase + g + (r >> 1) * 8;
                    int col = f * 8 + tg * 2 + (r & 1);
                    if (s == 0) sm->kb.ored[row][col] = accO[f][r];
                    else        sm->kb.ored[row][col] += accO[f][r];
                }
        }
        __syncthreads();
    }
    #pragma unroll
    for (int t = 0; t < 8; t++) {
        int job = tid + t * 512;
        int row = job >> 6, col = job & 63;
        float lt = sm->redl[row][0] + sm->redl[row][1] + sm->redl[row][2] + sm->redl[row][3];
        vec[((size_t)((i0 + row) * B_ + b)) * ND + n * DH + col] = sm->kb.ored[row][col] / lt;
    }
}

// ---------------- layernorm (optional fused residual add) ----------------
__global__ void ln_kernel(const float* __restrict__ x, const float* __restrict__ res,
                          const float* __restrict__ g, const float* __restrict__ b,
                          float* __restrict__ out)
{
    __shared__ float red[256];
    const int row = blockIdx.x, tid = threadIdx.x;
    const float* xr = x + (size_t)row * D_;
    float v[4];
    float s = 0.f;
    #pragma unroll
    for (int t = 0; t < 4; t++) {
        int d = tid + t * 256;
        v[t] = xr[d];
        if (res) v[t] += res[(size_t)row * D_ + d];
        s += v[t];
    }
    red[tid] = s; __syncthreads();
    for (int o = 128; o > 0; o >>= 1) { if (tid < o) red[tid] += red[tid + o]; __syncthreads(); }
    float mean = red[0] * (1.f / D_);
    __syncthreads();
    s = 0.f;
    #pragma unroll
    for (int t = 0; t < 4; t++) { float d2 = v[t] - mean; s += d2 * d2; }
    red[tid] = s; __syncthreads();
    for (int o = 128; o > 0; o >>= 1) { if (tid < o) red[tid] += red[tid + o]; __syncthreads(); }
    float inv = rsqrtf(red[0] * (1.f / D_) + 1e-12f);
    #pragma unroll
    for (int t = 0; t < 4; t++) {
        int d = tid + t * 256;
        out[(size_t)row * D_ + d] = (v[t] - mean) * inv * g[d] + b[d];
    }
}

// ---------------- host ----------------
static float* sym_addr(const void* sym) {
    void* p = nullptr;
    cudaGetSymbolAddress(&p, sym);
    return (float*)p;
}

extern "C" void kernel_launch(void* const* d_in, const int* in_sizes, int n_in,
                              void* d_out, int out_size)
{
    (void)in_sizes; (void)n_in; (void)out_size;
    const float* h         = (const float*)d_in[0];
    const float* pos_emb   = (const float*)d_in[1];
    const float* seg_mat   = (const float*)d_in[3];
    const float* Wq        = (const float*)d_in[4];
    const float* Wk        = (const float*)d_in[5];
    const float* Wv        = (const float*)d_in[6];
    const float* Wo        = (const float*)d_in[7];
    const float* Wr        = (const float*)d_in[8];
    const float* rw        = (const float*)d_in[9];
    const float* rr        = (const float*)d_in[10];
    const float* rs        = (const float*)d_in[11];
    const float* se        = (const float*)d_in[12];
    const float* ln1g      = (const float*)d_in[13];
    const float* ln1b      = (const float*)d_in[14];
    const float* w1        = (const float*)d_in[15];
    const float* b1        = (const float*)d_in[16];
    const float* w2        = (const float*)d_in[17];
    const float* b2        = (const float*)d_in[18];
    const float* ln2g      = (const float*)d_in[19];
    const float* ln2b      = (const float*)d_in[20];
    float* out = (float*)d_out;

    float* gq    = sym_addr(g_q);
    float* gk    = sym_addr(g_k);
    float* gv    = sym_addr(g_v);
    float* gkr   = sym_addr(g_kr);
    float* gef   = sym_addr(g_ef);
    float* gvec  = sym_addr(g_vec);
    float* gattn = sym_addr(g_attn);
    float* gx    = sym_addr(g_x);
    float* gf    = sym_addr(g_f);
    float* gf2   = sym_addr(g_f2);
    float* gbuf  = sym_addr(g_buf);

    static bool attr_set = false;
    if (!attr_set) {
        cudaFuncSetAttribute(flash_attn, cudaFuncAttributeMaxDynamicSharedMemorySize,
                             (int)sizeof(FlashSmem));
        attr_set = true;
    }

    for (int l = 0; l < 2; l++) {
        const float* cur = (l == 0) ? h : gbuf;
        float* nxt = (l == 0) ? gbuf : out;
        const size_t woff = (size_t)l * D_ * ND;

        tgemm_qkv<<<dim3(ND / 128, SB / 128, 3), 256>>>(
            cur, Wq + woff, Wk + woff, Wv + woff, gq, gk, gv);
        // only kr rows [0, KRR) are consumed downstream
        tgemm<EPI_NONE, false><<<dim3(ND / 128, (KRR * B_) / 128), 256>>>(
            pos_emb, Wr + woff, gkr, KRR * B_, ND, D_, nullptr, nullptr);

        ef_kernel<<<SB * NH / 4, 128>>>(gq, rs + l * NH * DH, se + l * 2 * NH * DH, gef);

        flash_attn<<<dim3(NHEADS, S_ / 64), 512, sizeof(FlashSmem)>>>(
            gq, gk, gkr, gv, rw + l * NH * DH, rr + l * NH * DH,
            gef, seg_mat, gvec);

        tgemm<EPI_RES, true><<<dim3(D_ / 128, SB / 128), 256>>>(
            gvec, Wo + woff, gattn, SB, D_, ND, nullptr, cur);

        ln_kernel<<<SB, 256>>>(gattn, nullptr, ln1g + l * D_, ln1b + l * D_, gx);

        tgemm<EPI_BIAS_GELU, false><<<dim3(DI_ / 128, SB / 128), 256>>>(
            gx, w1 + (size_t)l * D_ * DI_, gf, SB, DI_, D_, b1 + l * DI_, nullptr);

        tgemm<EPI_BIAS, false><<<dim3(D_ / 128, SB / 128), 256>>>(
            gf, w2 + (size_t)l * DI_ * D_, gf2, SB, D_, DI_, b2 + l * D_, nullptr);

        ln_kernel<<<SB, 256>>>(gf2, gx, ln2g + l * D_, ln2b + l * D_, nxt);
    }
}